// round 4
// baseline (speedup 1.0000x reference)
#include <cuda_runtime.h>
#include <math.h>
#include <stdint.h>

#define BATCH 4
#define SEQ   512
#define TOKS  (BATCH*SEQ)      // 2048
#define DH    1600
#define NHEADS 50
#define PH    32
#define NREL  100
#define KT    64               // key tile in attention

// ------------------------------------------------------------------
// Scratch (static __device__ — no allocation allowed)
// ------------------------------------------------------------------
__device__ float g_Q[TOKS*DH];
__device__ float g_K[TOKS*DH];
__device__ float g_V[TOKS*DH];
__device__ float g_ctx[TOKS*DH];
__device__ float g_attn[TOKS*DH];
__device__ float g_h1[TOKS*DH];

// ------------------------------------------------------------------
// SGEMM: C[M,N] = A[M,K] @ B[K,N] + bias[N], optional exact GELU.
// BM=128, BN=64, BK=16, 128 threads, 8x8 per-thread microtile.
// All dims are exact multiples (M=2048, N=1600, K=1600) -> no bounds checks.
// ------------------------------------------------------------------
__global__ __launch_bounds__(128) void sgemm_bias_act(
    const float* __restrict__ A, const float* __restrict__ B,
    const float* __restrict__ bias, float* __restrict__ C,
    int M, int N, int K, int act)
{
    __shared__ float As[16][128];   // transposed A tile: As[k][m]
    __shared__ float Bs[16][64];    // Bs[k][n]

    const int tid = threadIdx.x;
    const int tx  = tid & 7;        // 0..7  -> 8 cols of 8
    const int ty  = tid >> 3;       // 0..15 -> 16 rows of 8
    const int bm  = blockIdx.y * 128;
    const int bn  = blockIdx.x * 64;

    float acc[8][8];
    #pragma unroll
    for (int i = 0; i < 8; ++i)
        #pragma unroll
        for (int j = 0; j < 8; ++j) acc[i][j] = 0.f;

    // A-tile load mapping: 512 float4 total, 4 per thread
    const int arow0 = tid >> 2;         // row = f/4, f = tid + 128*i
    const int akc   = (tid & 3) * 4;    // k offset within tile
    // B-tile load mapping: 256 float4 total, 2 per thread
    const int brow0 = tid >> 4;         // row = f/16
    const int bnc   = (tid & 15) * 4;   // n offset within tile

    for (int k0 = 0; k0 < K; k0 += 16) {
        #pragma unroll
        for (int i = 0; i < 4; ++i) {
            int row = arow0 + i * 32;
            float4 v = *(const float4*)(A + (size_t)(bm + row) * K + k0 + akc);
            As[akc + 0][row] = v.x;
            As[akc + 1][row] = v.y;
            As[akc + 2][row] = v.z;
            As[akc + 3][row] = v.w;
        }
        #pragma unroll
        for (int i = 0; i < 2; ++i) {
            int row = brow0 + i * 8;
            float4 v = *(const float4*)(B + (size_t)(k0 + row) * N + bn + bnc);
            *(float4*)&Bs[row][bnc] = v;
        }
        __syncthreads();

        #pragma unroll
        for (int kk = 0; kk < 16; ++kk) {
            float a[8], bb[8];
            *(float4*)&a[0]  = *(const float4*)&As[kk][ty * 8];
            *(float4*)&a[4]  = *(const float4*)&As[kk][ty * 8 + 4];
            *(float4*)&bb[0] = *(const float4*)&Bs[kk][tx * 8];
            *(float4*)&bb[4] = *(const float4*)&Bs[kk][tx * 8 + 4];
            #pragma unroll
            for (int i = 0; i < 8; ++i)
                #pragma unroll
                for (int j = 0; j < 8; ++j)
                    acc[i][j] = fmaf(a[i], bb[j], acc[i][j]);
        }
        __syncthreads();
    }

    #pragma unroll
    for (int i = 0; i < 8; ++i) {
        int row = bm + ty * 8 + i;
        #pragma unroll
        for (int j = 0; j < 8; ++j) {
            float x = acc[i][j] + bias[bn + tx * 8 + j];
            if (act) {
                // exact GELU: 0.5*x*(1+erf(x/sqrt(2)))
                x = 0.5f * x * (1.f + erff(x * 0.70710678118654752f));
            }
            acc[i][j] = x;
        }
        *(float4*)(C + (size_t)row * N + bn + tx * 8)     = *(float4*)&acc[i][0];
        *(float4*)(C + (size_t)row * N + bn + tx * 8 + 4) = *(float4*)&acc[i][4];
    }
}

// ------------------------------------------------------------------
// Fused relation-aware attention. One query per thread; flash-style
// online softmax. rel_k/rel_v embedding tables live in SMEM (stride
// PH+1=33 so per-thread relation gathers land on distinct banks:
// bank = (r + d) mod 32).
//   score[q,k] = (q . (K[k] + rel_k[rm[b,q,k]])) / sqrt(PH)
//   ctx[q]     = sum_k softmax(score) * (V[k] + rel_v[rm[b,q,k]])
// ------------------------------------------------------------------
__global__ __launch_bounds__(256, 2) void attn_kernel(
    const float* __restrict__ Q, const float* __restrict__ Kg,
    const float* __restrict__ Vg,
    const float* __restrict__ relk, const float* __restrict__ relv,
    const int* __restrict__ rm, float* __restrict__ ctxout)
{
    __shared__ float Ks[KT][PH];
    __shared__ float Vs[KT][PH];
    __shared__ float rk[NREL][PH + 1];
    __shared__ float rv[NREL][PH + 1];

    const int bh  = blockIdx.x;
    const int b   = bh / NHEADS;
    const int h   = bh % NHEADS;
    const int tid = threadIdx.x;
    const int q   = blockIdx.y * 256 + tid;

    // stage relation embedding tables (100x32 each)
    for (int i = tid; i < NREL * PH; i += 256) {
        int r = i >> 5, d = i & 31;
        rk[r][d] = relk[i];
        rv[r][d] = relv[i];
    }

    // per-thread query vector
    float qv[PH];
    {
        const float* qp = Q + (size_t)(b * SEQ + q) * DH + h * PH;
        #pragma unroll
        for (int d = 0; d < PH; d += 4) {
            float4 t = *(const float4*)(qp + d);
            qv[d] = t.x; qv[d + 1] = t.y; qv[d + 2] = t.z; qv[d + 3] = t.w;
        }
    }

    float m = -1e30f, l = 0.f;
    float ctx[PH];
    #pragma unroll
    for (int d = 0; d < PH; ++d) ctx[d] = 0.f;

    const float scale = 0.1767766952966369f;  // 1/sqrt(32)
    const int* rmrow = rm + ((size_t)b * SEQ + q) * SEQ;

    for (int kt = 0; kt < SEQ; kt += KT) {
        __syncthreads();
        // load K/V tile: KT*PH floats each, float4-vectorized, coalesced
        for (int f = tid; f < KT * PH / 4; f += 256) {
            int row = f >> 3;
            int c   = (f & 7) * 4;
            size_t gidx = (size_t)(b * SEQ + kt + row) * DH + h * PH + c;
            ((float4*)Ks)[f] = *(const float4*)(Kg + gidx);
            ((float4*)Vs)[f] = *(const float4*)(Vg + gidx);
        }
        __syncthreads();

        for (int kk0 = 0; kk0 < KT; kk0 += 8) {
            int rr[8];
            float s[8];
            {
                int4 t0 = *(const int4*)(rmrow + kt + kk0);
                int4 t1 = *(const int4*)(rmrow + kt + kk0 + 4);
                rr[0] = t0.x; rr[1] = t0.y; rr[2] = t0.z; rr[3] = t0.w;
                rr[4] = t1.x; rr[5] = t1.y; rr[6] = t1.z; rr[7] = t1.w;
            }
            float tmax = -1e30f;
            #pragma unroll
            for (int j = 0; j < 8; ++j) {
                const float* kv  = Ks[kk0 + j];   // broadcast across warp
                const float* rkv = rk[rr[j]];     // bank-spread gather
                float a = 0.f;
                #pragma unroll
                for (int d = 0; d < PH; ++d)
                    a = fmaf(qv[d], kv[d] + rkv[d], a);
                s[j] = a * scale;
                tmax = fmaxf(tmax, s[j]);
            }
            if (tmax > m) {
                float alpha = __expf(m - tmax);
                m = tmax;
                l *= alpha;
                #pragma unroll
                for (int d = 0; d < PH; ++d) ctx[d] *= alpha;
            }
            #pragma unroll
            for (int j = 0; j < 8; ++j) {
                float p = __expf(s[j] - m);
                l += p;
                const float* vv  = Vs[kk0 + j];
                const float* rvv = rv[rr[j]];
                #pragma unroll
                for (int d = 0; d < PH; ++d)
                    ctx[d] = fmaf(p, vv[d] + rvv[d], ctx[d]);
            }
        }
    }

    float inv = 1.f / l;
    float* op = ctxout + (size_t)(b * SEQ + q) * DH + h * PH;
    #pragma unroll
    for (int d = 0; d < PH; d += 4) {
        float4 t;
        t.x = ctx[d] * inv; t.y = ctx[d + 1] * inv;
        t.z = ctx[d + 2] * inv; t.w = ctx[d + 3] * inv;
        *(float4*)(op + d) = t;
    }
}

// ------------------------------------------------------------------
// Launch: 3 projection GEMMs -> attention -> Wo -> W1(+gelu) -> W2
// All on the default stream; graph-capturable (launches only).
// ------------------------------------------------------------------
extern "C" void kernel_launch(void* const* d_in, const int* in_sizes, int n_in,
                              void* d_out, int out_size)
{
    const float* hidden = (const float*)d_in[0];
    const float* Wq = (const float*)d_in[1];
    const float* bq = (const float*)d_in[2];
    const float* Wk = (const float*)d_in[3];
    const float* bk = (const float*)d_in[4];
    const float* Wv = (const float*)d_in[5];
    const float* bv = (const float*)d_in[6];
    const float* Wo = (const float*)d_in[7];
    const float* bo = (const float*)d_in[8];
    const float* rke = (const float*)d_in[9];
    const float* rve = (const float*)d_in[10];
    const float* W1 = (const float*)d_in[11];
    const float* b1 = (const float*)d_in[12];
    const float* W2 = (const float*)d_in[13];
    const float* b2 = (const float*)d_in[14];
    const int*   rm = (const int*)d_in[15];
    float* out = (float*)d_out;

    float *Qb, *Kb, *Vb, *Cb, *Ab, *Hb;
    cudaGetSymbolAddress((void**)&Qb, g_Q);
    cudaGetSymbolAddress((void**)&Kb, g_K);
    cudaGetSymbolAddress((void**)&Vb, g_V);
    cudaGetSymbolAddress((void**)&Cb, g_ctx);
    cudaGetSymbolAddress((void**)&Ab, g_attn);
    cudaGetSymbolAddress((void**)&Hb, g_h1);

    dim3 gg(DH / 64, TOKS / 128);   // (25, 16)

    sgemm_bias_act<<<gg, 128>>>(hidden, Wq, bq, Qb, TOKS, DH, DH, 0);
    sgemm_bias_act<<<gg, 128>>>(hidden, Wk, bk, Kb, TOKS, DH, DH, 0);
    sgemm_bias_act<<<gg, 128>>>(hidden, Wv, bv, Vb, TOKS, DH, DH, 0);

    dim3 ag(BATCH * NHEADS, SEQ / 256);  // (200, 2)
    attn_kernel<<<ag, 256>>>(Qb, Kb, Vb, rke, rve, rm, Cb);

    sgemm_bias_act<<<gg, 128>>>(Cb, Wo, bo, Ab, TOKS, DH, DH, 0);
    sgemm_bias_act<<<gg, 128>>>(Ab, W1, b1, Hb, TOKS, DH, DH, 1);
    sgemm_bias_act<<<gg, 128>>>(Hb, W2, b2, out, TOKS, DH, DH, 0);
}

// round 5
// speedup vs baseline: 1.0914x; 1.0914x over previous
#include <cuda_runtime.h>
#include <cuda_bf16.h>
#include <math.h>
#include <stdint.h>

#define BATCH 4
#define SEQ   512
#define TOKS  (BATCH*SEQ)      // 2048
#define DH    1600
#define NHEADS 50
#define PH    32
#define NREL  100

// ---------------- static scratch (no allocation allowed) ----------------
__device__ float g_Q[TOKS*DH];
__device__ float g_K[TOKS*DH];
__device__ float g_V[TOKS*DH];
__device__ float g_ctx[TOKS*DH];
__device__ float g_attn[TOKS*DH];
__device__ float g_h1[TOKS*DH];
// transposed bf16 hi/lo weights: [6][N=1600][K=1600]
__device__ __nv_bfloat16 g_Wh[6][DH*DH];
__device__ __nv_bfloat16 g_Wl[6][DH*DH];

// ------------- weight convert: W[K][N] fp32 -> [N][K] bf16 hi/lo --------
__global__ __launch_bounds__(256) void convert_weight(
    const float* __restrict__ W,
    __nv_bfloat16* __restrict__ hi, __nv_bfloat16* __restrict__ lo)
{
    __shared__ float t[32][33];
    const int n0 = blockIdx.x * 32, k0 = blockIdx.y * 32;
    const int tx = threadIdx.x, ty = threadIdx.y;   // (32,8)
    #pragma unroll
    for (int j = 0; j < 32; j += 8)
        t[ty + j][tx] = W[(size_t)(k0 + ty + j) * DH + n0 + tx];
    __syncthreads();
    #pragma unroll
    for (int j = 0; j < 32; j += 8) {
        float v = t[tx][ty + j];
        __nv_bfloat16 h = __float2bfloat16(v);
        __nv_bfloat16 l = __float2bfloat16(v - __bfloat162float(h));
        size_t o = (size_t)(n0 + ty + j) * DH + k0 + tx;
        hi[o] = h; lo[o] = l;
    }
}

// ------------- bf16x3 tensor-core GEMM --------------------------------
// C[M=2048,N=1600] = A(fp32) @ W + bias (optional exact GELU)
// BM=128 BN=80 BK=32, 256 thr = 8 warps (4m x 2n), warp tile 32x40.
__device__ __forceinline__ uint32_t packbf(__nv_bfloat16 a, __nv_bfloat16 b) {
    return (uint32_t)__bfloat16_as_ushort(a) |
           ((uint32_t)__bfloat16_as_ushort(b) << 16);
}
__device__ __forceinline__ void mma16816(float* c, const uint32_t* a,
                                         uint32_t b0, uint32_t b1) {
    asm volatile(
        "mma.sync.aligned.m16n8k16.row.col.f32.bf16.bf16.f32 "
        "{%0,%1,%2,%3}, {%4,%5,%6,%7}, {%8,%9}, {%0,%1,%2,%3};"
        : "+f"(c[0]), "+f"(c[1]), "+f"(c[2]), "+f"(c[3])
        : "r"(a[0]), "r"(a[1]), "r"(a[2]), "r"(a[3]), "r"(b0), "r"(b1));
}

__global__ __launch_bounds__(256, 2) void hgemm3(
    const float* __restrict__ A,
    const __nv_bfloat16* __restrict__ Bh, const __nv_bfloat16* __restrict__ Bl,
    const float* __restrict__ bias, float* __restrict__ C, int act)
{
    __shared__ __align__(16) uint32_t As[2][128 * 20];  // [hi/lo][row][20 words]
    __shared__ __align__(16) uint32_t Bs[2][80 * 20];

    const int tid  = threadIdx.x;
    const int lane = tid & 31, warp = tid >> 5;
    const int wm = warp >> 1, wn = warp & 1;
    const int g = lane >> 2, t4 = lane & 3;
    const int bm = blockIdx.y * 128, bn = blockIdx.x * 80;

    float acc[2][5][4];
    #pragma unroll
    for (int mt = 0; mt < 2; ++mt)
        #pragma unroll
        for (int nt = 0; nt < 5; ++nt)
            #pragma unroll
            for (int i = 0; i < 4; ++i) acc[mt][nt][i] = 0.f;

    for (int k0 = 0; k0 < DH; k0 += 32) {
        // stage A tile (fp32 -> hi/lo bf16 pairs), 1024 float4 loads
        for (int idx = tid; idx < 1024; idx += 256) {
            int r = idx >> 3, kq = idx & 7;
            float4 v = *(const float4*)(A + (size_t)(bm + r) * DH + k0 + kq * 4);
            __nv_bfloat16 hx = __float2bfloat16(v.x), hy = __float2bfloat16(v.y);
            __nv_bfloat16 hz = __float2bfloat16(v.z), hw = __float2bfloat16(v.w);
            As[0][r * 20 + kq * 2]     = packbf(hx, hy);
            As[0][r * 20 + kq * 2 + 1] = packbf(hz, hw);
            As[1][r * 20 + kq * 2]     = packbf(
                __float2bfloat16(v.x - __bfloat162float(hx)),
                __float2bfloat16(v.y - __bfloat162float(hy)));
            As[1][r * 20 + kq * 2 + 1] = packbf(
                __float2bfloat16(v.z - __bfloat162float(hz)),
                __float2bfloat16(v.w - __bfloat162float(hw)));
        }
        // stage B tile: 80 rows x 16 words = 320 uint4
        for (int idx = tid; idx < 320; idx += 256) {
            int r = idx >> 2, c = idx & 3;
            size_t off = (size_t)(bn + r) * DH + k0 + c * 8;
            *(uint4*)&Bs[0][r * 20 + c * 4] = *(const uint4*)(Bh + off);
            *(uint4*)&Bs[1][r * 20 + c * 4] = *(const uint4*)(Bl + off);
        }
        __syncthreads();

        #pragma unroll
        for (int ks = 0; ks < 16; ks += 8) {   // two k16 halves
            uint32_t ah[2][4], al[2][4];
            #pragma unroll
            for (int mt = 0; mt < 2; ++mt) {
                int base = (wm * 32 + mt * 16 + g) * 20 + ks + t4;
                ah[mt][0] = As[0][base];       ah[mt][1] = As[0][base + 160];
                ah[mt][2] = As[0][base + 4];   ah[mt][3] = As[0][base + 164];
                al[mt][0] = As[1][base];       al[mt][1] = As[1][base + 160];
                al[mt][2] = As[1][base + 4];   al[mt][3] = As[1][base + 164];
            }
            #pragma unroll
            for (int nt = 0; nt < 5; ++nt) {
                int bb = (wn * 40 + nt * 8 + g) * 20 + ks + t4;
                uint32_t bh0 = Bs[0][bb], bh1 = Bs[0][bb + 4];
                uint32_t bl0 = Bs[1][bb], bl1 = Bs[1][bb + 4];
                #pragma unroll
                for (int mt = 0; mt < 2; ++mt) {
                    mma16816(acc[mt][nt], ah[mt], bh0, bh1);
                    mma16816(acc[mt][nt], ah[mt], bl0, bl1);
                    mma16816(acc[mt][nt], al[mt], bh0, bh1);
                }
            }
        }
        __syncthreads();
    }

    #pragma unroll
    for (int mt = 0; mt < 2; ++mt) {
        #pragma unroll
        for (int nt = 0; nt < 5; ++nt) {
            int r0 = bm + wm * 32 + mt * 16 + g;
            int c0 = bn + wn * 40 + nt * 8 + t4 * 2;
            float b0v = bias[c0], b1v = bias[c0 + 1];
            float x0 = acc[mt][nt][0] + b0v, x1 = acc[mt][nt][1] + b1v;
            float x2 = acc[mt][nt][2] + b0v, x3 = acc[mt][nt][3] + b1v;
            if (act) {
                x0 = 0.5f * x0 * (1.f + erff(x0 * 0.70710678118654752f));
                x1 = 0.5f * x1 * (1.f + erff(x1 * 0.70710678118654752f));
                x2 = 0.5f * x2 * (1.f + erff(x2 * 0.70710678118654752f));
                x3 = 0.5f * x3 * (1.f + erff(x3 * 0.70710678118654752f));
            }
            *(float2*)(C + (size_t)r0 * DH + c0)       = make_float2(x0, x1);
            *(float2*)(C + (size_t)(r0 + 8) * DH + c0) = make_float2(x2, x3);
        }
    }
}

// ------------- attention: warp-per-query, two-pass --------------------
// smem floats: relk 3300 | relv 3300 | kv 2112 | sc 4096 | qrel 800 |
//              mass 800 | tmp 256  = 14664 (58656 B, dynamic)
#define ATTN_SMEM (14664 * 4)

__global__ __launch_bounds__(256, 2) void attn_v2(
    const float* __restrict__ Q, const float* __restrict__ Kg,
    const float* __restrict__ Vg,
    const float* __restrict__ relk, const float* __restrict__ relv,
    const int* __restrict__ rm, float* __restrict__ ctxout)
{
    extern __shared__ float sm[];
    float* relk_s = sm;                 // [100][33]
    float* relv_s = sm + 3300;          // [100][33]
    float* kv_s   = sm + 6600;          // [64][33]
    float* sc_s   = sm + 8712;          // [8][512]
    float* qrel_s = sm + 12808;         // [8][100]
    float* mass_s = sm + 13608;         // [8][100]
    float* tmp_s  = sm + 14408;         // [8][32]

    const int tid  = threadIdx.x;
    const int w    = tid >> 5, lane = tid & 31;
    const int b    = blockIdx.x / NHEADS, h = blockIdx.x % NHEADS;
    const int q    = blockIdx.y * 8 + w;
    const float scale = 0.1767766952966369f;  // 1/sqrt(32)

    for (int i = tid; i < NREL * PH; i += 256) {
        int r = i >> 5, d = i & 31;
        relk_s[r * 33 + d] = relk[i];
        relv_s[r * 33 + d] = relv[i];
    }
    tmp_s[tid] = Q[(size_t)(b * SEQ + q) * DH + h * PH + lane];
    __syncthreads();

    float qv[PH];
    #pragma unroll
    for (int d = 0; d < PH; ++d) qv[d] = tmp_s[w * 32 + d] * scale;

    for (int r = lane; r < NREL; r += 32) {
        float a = 0.f;
        #pragma unroll
        for (int d = 0; d < PH; ++d) a = fmaf(qv[d], relk_s[r * 33 + d], a);
        qrel_s[w * 100 + r] = a;
        mass_s[w * 100 + r] = 0.f;
    }
    __syncwarp();

    const int* rmrow = rm + ((size_t)(b * SEQ + q)) * SEQ;

    // pass A: scores + running max
    float mloc = -1e30f;
    for (int kt = 0; kt < SEQ; kt += 64) {
        __syncthreads();
        for (int i = tid; i < 64 * PH; i += 256) {
            int row = i >> 5, d = i & 31;
            kv_s[row * 33 + d] = Kg[(size_t)(b * SEQ + kt + row) * DH + h * PH + d];
        }
        __syncthreads();
        #pragma unroll
        for (int c = 0; c < 64; c += 32) {
            int key = kt + c + lane;
            const float* kp = &kv_s[(c + lane) * 33];
            float s = 0.f;
            #pragma unroll
            for (int d = 0; d < PH; ++d) s = fmaf(qv[d], kp[d], s);
            s += qrel_s[w * 100 + rmrow[key]];
            sc_s[w * 512 + key] = s;
            mloc = fmaxf(mloc, s);
        }
    }
    #pragma unroll
    for (int off = 16; off > 0; off >>= 1)
        mloc = fmaxf(mloc, __shfl_xor_sync(0xffffffffu, mloc, off));

    // pass B: probs -> ctx and relation-mass histogram
    float l = 0.f;
    float ctx[PH];
    #pragma unroll
    for (int d = 0; d < PH; ++d) ctx[d] = 0.f;

    for (int kt = 0; kt < SEQ; kt += 64) {
        __syncthreads();
        for (int i = tid; i < 64 * PH; i += 256) {
            int row = i >> 5, d = i & 31;
            kv_s[row * 33 + d] = Vg[(size_t)(b * SEQ + kt + row) * DH + h * PH + d];
        }
        __syncthreads();
        #pragma unroll
        for (int c = 0; c < 64; c += 32) {
            int key = kt + c + lane;
            float p = __expf(sc_s[w * 512 + key] - mloc);
            l += p;
            atomicAdd(&mass_s[w * 100 + rmrow[key]], p);
            const float* vp = &kv_s[(c + lane) * 33];
            #pragma unroll
            for (int d = 0; d < PH; ++d) ctx[d] = fmaf(p, vp[d], ctx[d]);
        }
    }

    #pragma unroll
    for (int off = 16; off > 0; off >>= 1) {
        l += __shfl_xor_sync(0xffffffffu, l, off);
        #pragma unroll
        for (int d = 0; d < PH; ++d)
            ctx[d] += __shfl_xor_sync(0xffffffffu, ctx[d], off);
    }
    __syncwarp();

    if (lane == 0) {
        #pragma unroll
        for (int d = 0; d < PH; ++d) tmp_s[w * 32 + d] = ctx[d];
    }
    __syncwarp();

    // lane d finalizes output dim d:  (ctx[d] + sum_r mass[r]*rel_v[r][d]) / l
    float cd = tmp_s[w * 32 + lane];
    float racc = 0.f;
    #pragma unroll 4
    for (int r = 0; r < NREL; ++r)
        racc = fmaf(mass_s[w * 100 + r], relv_s[r * 33 + lane], racc);

    ctxout[(size_t)(b * SEQ + q) * DH + h * PH + lane] = (cd + racc) / l;
}

// ----------------------------- launch ---------------------------------
extern "C" void kernel_launch(void* const* d_in, const int* in_sizes, int n_in,
                              void* d_out, int out_size)
{
    const float* hidden = (const float*)d_in[0];
    const float* Wq = (const float*)d_in[1];
    const float* bq = (const float*)d_in[2];
    const float* Wk = (const float*)d_in[3];
    const float* bk = (const float*)d_in[4];
    const float* Wv = (const float*)d_in[5];
    const float* bv = (const float*)d_in[6];
    const float* Wo = (const float*)d_in[7];
    const float* bo = (const float*)d_in[8];
    const float* rke = (const float*)d_in[9];
    const float* rve = (const float*)d_in[10];
    const float* W1 = (const float*)d_in[11];
    const float* b1 = (const float*)d_in[12];
    const float* W2 = (const float*)d_in[13];
    const float* b2 = (const float*)d_in[14];
    const int*   rm = (const int*)d_in[15];
    float* out = (float*)d_out;

    float *Qb, *Kb, *Vb, *Cb, *Ab, *Hb;
    cudaGetSymbolAddress((void**)&Qb, g_Q);
    cudaGetSymbolAddress((void**)&Kb, g_K);
    cudaGetSymbolAddress((void**)&Vb, g_V);
    cudaGetSymbolAddress((void**)&Cb, g_ctx);
    cudaGetSymbolAddress((void**)&Ab, g_attn);
    cudaGetSymbolAddress((void**)&Hb, g_h1);
    __nv_bfloat16 *Wh, *Wl;
    cudaGetSymbolAddress((void**)&Wh, g_Wh);
    cudaGetSymbolAddress((void**)&Wl, g_Wl);

    static int attr_done = 0;
    if (!attr_done) {
        cudaFuncSetAttribute(attn_v2,
            cudaFuncAttributeMaxDynamicSharedMemorySize, ATTN_SMEM);
        attr_done = 1;
    }

    // convert all six weights (transposed, bf16 hi/lo split)
    dim3 cb(32, 8), cg(DH / 32, DH / 32);
    const float* Ws[6] = {Wq, Wk, Wv, Wo, W1, W2};
    for (int i = 0; i < 6; ++i)
        convert_weight<<<cg, cb>>>(Ws[i], Wh + (size_t)i * DH * DH,
                                   Wl + (size_t)i * DH * DH);

    dim3 gg(DH / 80, TOKS / 128);   // (20, 16)
    size_t WW = (size_t)DH * DH;

    hgemm3<<<gg, 256>>>(hidden, Wh + 0 * WW, Wl + 0 * WW, bq, Qb, 0);
    hgemm3<<<gg, 256>>>(hidden, Wh + 1 * WW, Wl + 1 * WW, bk, Kb, 0);
    hgemm3<<<gg, 256>>>(hidden, Wh + 2 * WW, Wl + 2 * WW, bv, Vb, 0);

    dim3 ag(BATCH * NHEADS, SEQ / 8);  // (200, 64)
    attn_v2<<<ag, 256, ATTN_SMEM>>>(Qb, Kb, Vb, rke, rve, rm, Cb);

    hgemm3<<<gg, 256>>>(Cb, Wh + 3 * WW, Wl + 3 * WW, bo, Ab, 0);
    hgemm3<<<gg, 256>>>(Ab, Wh + 4 * WW, Wl + 4 * WW, b1, Hb, 1);
    hgemm3<<<gg, 256>>>(Hb, Wh + 5 * WW, Wl + 5 * WW, b2, out, 0);
}

// round 7
// speedup vs baseline: 1.5726x; 1.4410x over previous
#include <cuda_runtime.h>
#include <cuda_bf16.h>
#include <math.h>
#include <stdint.h>

#define BATCH 4
#define SEQ   512
#define TOKS  (BATCH*SEQ)      // 2048
#define DH    1600
#define NHEADS 50
#define PH    32
#define NREL  100

// ---------------- static scratch (no allocation allowed) ----------------
__device__ float g_Q[TOKS*DH];
__device__ float g_K[TOKS*DH];
__device__ float g_V[TOKS*DH];
// bf16 hi/lo activation buffers (row-major [M][DH])
__device__ __nv_bfloat16 g_hh[TOKS*DH], g_hl[TOKS*DH];   // hidden split
__device__ __nv_bfloat16 g_ch[TOKS*DH], g_cl[TOKS*DH];   // ctx split
__device__ __nv_bfloat16 g_ah[TOKS*DH], g_al[TOKS*DH];   // attn_out split
__device__ __nv_bfloat16 g_1h[TOKS*DH], g_1l[TOKS*DH];   // h1 split
// transposed bf16 hi/lo weights: [6][N=1600][K=1600]
__device__ __nv_bfloat16 g_Wh[6][DH*DH];
__device__ __nv_bfloat16 g_Wl[6][DH*DH];

// ------------- batched weight convert: W[K][N] fp32 -> [N][K] bf16 hi/lo
__global__ __launch_bounds__(256) void convert_weight6(
    const float* W0, const float* W1, const float* W2,
    const float* W3, const float* W4, const float* W5,
    __nv_bfloat16* __restrict__ hi_base, __nv_bfloat16* __restrict__ lo_base)
{
    __shared__ float t[32][33];
    const int wi = blockIdx.z;
    const float* W = (wi == 0) ? W0 : (wi == 1) ? W1 : (wi == 2) ? W2 :
                     (wi == 3) ? W3 : (wi == 4) ? W4 : W5;
    __nv_bfloat16* hi = hi_base + (size_t)wi * DH * DH;
    __nv_bfloat16* lo = lo_base + (size_t)wi * DH * DH;
    const int n0 = blockIdx.x * 32, k0 = blockIdx.y * 32;
    const int tx = threadIdx.x, ty = threadIdx.y;   // (32,8)
    #pragma unroll
    for (int j = 0; j < 32; j += 8)
        t[ty + j][tx] = W[(size_t)(k0 + ty + j) * DH + n0 + tx];
    __syncthreads();
    #pragma unroll
    for (int j = 0; j < 32; j += 8) {
        float v = t[tx][ty + j];
        __nv_bfloat16 h = __float2bfloat16(v);
        __nv_bfloat16 l = __float2bfloat16(v - __bfloat162float(h));
        size_t o = (size_t)(n0 + ty + j) * DH + k0 + tx;
        hi[o] = h; lo[o] = l;
    }
}

// ------------- activation split: fp32 -> bf16 hi/lo ---------------------
__global__ __launch_bounds__(256) void split_act(
    const float* __restrict__ x,
    __nv_bfloat16* __restrict__ hi, __nv_bfloat16* __restrict__ lo)
{
    size_t i = ((size_t)blockIdx.x * 256 + threadIdx.x) * 4;
    float4 v = *(const float4*)(x + i);
    __nv_bfloat16 hx = __float2bfloat16(v.x), hy = __float2bfloat16(v.y);
    __nv_bfloat16 hz = __float2bfloat16(v.z), hw = __float2bfloat16(v.w);
    __nv_bfloat162 h01; h01.x = hx; h01.y = hy;
    __nv_bfloat162 h23; h23.x = hz; h23.y = hw;
    *(__nv_bfloat162*)(hi + i)     = h01;
    *(__nv_bfloat162*)(hi + i + 2) = h23;
    __nv_bfloat162 l01, l23;
    l01.x = __float2bfloat16(v.x - __bfloat162float(hx));
    l01.y = __float2bfloat16(v.y - __bfloat162float(hy));
    l23.x = __float2bfloat16(v.z - __bfloat162float(hz));
    l23.y = __float2bfloat16(v.w - __bfloat162float(hw));
    *(__nv_bfloat162*)(lo + i)     = l01;
    *(__nv_bfloat162*)(lo + i + 2) = l23;
}

// ------------- bf16x3 tensor-core GEMM, cp.async double-buffered --------
// C = (Ah+Al) @ (Bh+Bl)^T + bias;  D = Ah*Bh + Ah*Bl + Al*Bh (fp32 acc)
// BM=128 BN=80 BK=32, 256 thr = 8 warps (4m x 2n), warp tile 32x40.
// stage words: Ahi 2560 | Alo 2560 | Bhi 1600 | Blo 1600 = 8320
#define GSTAGE 8320
#define GSMEM  (2 * GSTAGE * 4)

__device__ __forceinline__ void mma16816(float* c, const uint32_t* a,
                                         uint32_t b0, uint32_t b1) {
    asm volatile(
        "mma.sync.aligned.m16n8k16.row.col.f32.bf16.bf16.f32 "
        "{%0,%1,%2,%3}, {%4,%5,%6,%7}, {%8,%9}, {%0,%1,%2,%3};"
        : "+f"(c[0]), "+f"(c[1]), "+f"(c[2]), "+f"(c[3])
        : "r"(a[0]), "r"(a[1]), "r"(a[2]), "r"(a[3]), "r"(b0), "r"(b1));
}
__device__ __forceinline__ void cpasync16(uint32_t dst, const void* src) {
    asm volatile("cp.async.cg.shared.global [%0], [%1], 16;"
                 :: "r"(dst), "l"(src));
}

__global__ __launch_bounds__(256, 2) void hgemm_v3(
    const __nv_bfloat16* __restrict__ Ah, const __nv_bfloat16* __restrict__ Al,
    const __nv_bfloat16* __restrict__ Bh, const __nv_bfloat16* __restrict__ Bl,
    const float* __restrict__ bias,
    float* __restrict__ Cf,
    __nv_bfloat16* __restrict__ Ch, __nv_bfloat16* __restrict__ Cl,
    int act, int mode)   // mode 0: fp32 out; mode 1: split bf16 out
{
    extern __shared__ uint32_t smw[];
    const uint32_t sm0 = (uint32_t)__cvta_generic_to_shared(smw);

    const int tid  = threadIdx.x;
    const int lane = tid & 31, warp = tid >> 5;
    const int wm = warp >> 1, wn = warp & 1;
    const int g = lane >> 2, t4 = lane & 3;
    const int bm = blockIdx.y * 128, bn = blockIdx.x * 80;

    float acc[2][5][4];
    #pragma unroll
    for (int mt = 0; mt < 2; ++mt)
        #pragma unroll
        for (int nt = 0; nt < 5; ++nt)
            #pragma unroll
            for (int i = 0; i < 4; ++i) acc[mt][nt][i] = 0.f;

    // ---- tile loader (cp.async, 16B = 8 bf16 chunks) ----
    auto load_tile = [&](int stage, int kk) {
        uint32_t sb = sm0 + stage * GSTAGE * 4;
        // A: 1024 chunks (hi 512 + lo 512), 4 per thread
        #pragma unroll
        for (int it = 0; it < 4; ++it) {
            int idx = tid + it * 256;
            int hl = idx >> 9;
            int r  = (idx >> 2) & 127;
            int c  = idx & 3;
            const __nv_bfloat16* src =
                (hl ? Al : Ah) + (size_t)(bm + r) * DH + kk + c * 8;
            cpasync16(sb + (hl * 2560 + r * 20 + c * 4) * 4, src);
        }
        // B: 640 chunks (hi 320 + lo 320)
        for (int idx = tid; idx < 640; idx += 256) {
            int hl = idx >= 320;
            int j  = idx - hl * 320;
            int r  = j >> 2, c = j & 3;
            const __nv_bfloat16* src =
                (hl ? Bl : Bh) + (size_t)(bn + r) * DH + kk + c * 8;
            cpasync16(sb + (5120 + hl * 1600 + r * 20 + c * 4) * 4, src);
        }
        asm volatile("cp.async.commit_group;");
    };

    load_tile(0, 0);

    const int NT = DH / 32;   // 50
    for (int t = 0; t < NT; ++t) {
        int cur = t & 1;
        if (t + 1 < NT) {
            load_tile(cur ^ 1, (t + 1) * 32);
            asm volatile("cp.async.wait_group 1;");
        } else {
            asm volatile("cp.async.wait_group 0;");
        }
        __syncthreads();

        const uint32_t* S  = smw + cur * GSTAGE;
        const uint32_t* A0 = S;           // A hi
        const uint32_t* A1 = S + 2560;    // A lo
        const uint32_t* B0 = S + 5120;    // B hi
        const uint32_t* B1 = S + 6720;    // B lo

        #pragma unroll
        for (int ks = 0; ks < 16; ks += 8) {   // two k16 halves of BK=32
            uint32_t ah[2][4], al[2][4];
            #pragma unroll
            for (int mt = 0; mt < 2; ++mt) {
                int base = (wm * 32 + mt * 16 + g) * 20 + ks + t4;
                ah[mt][0] = A0[base];     ah[mt][1] = A0[base + 160];
                ah[mt][2] = A0[base + 4]; ah[mt][3] = A0[base + 164];
                al[mt][0] = A1[base];     al[mt][1] = A1[base + 160];
                al[mt][2] = A1[base + 4]; al[mt][3] = A1[base + 164];
            }
            #pragma unroll
            for (int nt = 0; nt < 5; ++nt) {
                int bb = (wn * 40 + nt * 8 + g) * 20 + ks + t4;
                uint32_t bh0 = B0[bb], bh1 = B0[bb + 4];
                uint32_t bl0 = B1[bb], bl1 = B1[bb + 4];
                #pragma unroll
                for (int mt = 0; mt < 2; ++mt) {
                    mma16816(acc[mt][nt], ah[mt], bh0, bh1);
                    mma16816(acc[mt][nt], ah[mt], bl0, bl1);
                    mma16816(acc[mt][nt], al[mt], bh0, bh1);
                }
            }
        }
        __syncthreads();
    }

    // ---- epilogue (warp tile 32x40: cols wn*40 + nt*8, consistent) ----
    #pragma unroll
    for (int mt = 0; mt < 2; ++mt) {
        #pragma unroll
        for (int nt = 0; nt < 5; ++nt) {
            int r0 = bm + wm * 32 + mt * 16 + g;
            int c0 = bn + wn * 40 + nt * 8 + t4 * 2;
            float b0v = bias[c0], b1v = bias[c0 + 1];
            float x0 = acc[mt][nt][0] + b0v, x1 = acc[mt][nt][1] + b1v;
            float x2 = acc[mt][nt][2] + b0v, x3 = acc[mt][nt][3] + b1v;
            if (act) {
                x0 = 0.5f * x0 * (1.f + erff(x0 * 0.70710678118654752f));
                x1 = 0.5f * x1 * (1.f + erff(x1 * 0.70710678118654752f));
                x2 = 0.5f * x2 * (1.f + erff(x2 * 0.70710678118654752f));
                x3 = 0.5f * x3 * (1.f + erff(x3 * 0.70710678118654752f));
            }
            if (mode == 0) {
                *(float2*)(Cf + (size_t)r0 * DH + c0)       = make_float2(x0, x1);
                *(float2*)(Cf + (size_t)(r0 + 8) * DH + c0) = make_float2(x2, x3);
            } else {
                __nv_bfloat162 h01, h23, l01, l23;
                h01.x = __float2bfloat16(x0); h01.y = __float2bfloat16(x1);
                h23.x = __float2bfloat16(x2); h23.y = __float2bfloat16(x3);
                l01.x = __float2bfloat16(x0 - __bfloat162float(h01.x));
                l01.y = __float2bfloat16(x1 - __bfloat162float(h01.y));
                l23.x = __float2bfloat16(x2 - __bfloat162float(h23.x));
                l23.y = __float2bfloat16(x3 - __bfloat162float(h23.y));
                *(__nv_bfloat162*)(Ch + (size_t)r0 * DH + c0)       = h01;
                *(__nv_bfloat162*)(Ch + (size_t)(r0 + 8) * DH + c0) = h23;
                *(__nv_bfloat162*)(Cl + (size_t)r0 * DH + c0)       = l01;
                *(__nv_bfloat162*)(Cl + (size_t)(r0 + 8) * DH + c0) = l23;
            }
        }
    }
}

// ------------- attention: warp-per-query, two-pass ----------------------
#define ATTN_SMEM (14664 * 4)

__global__ __launch_bounds__(256, 2) void attn_v2(
    const float* __restrict__ Q, const float* __restrict__ Kg,
    const float* __restrict__ Vg,
    const float* __restrict__ relk, const float* __restrict__ relv,
    const int* __restrict__ rm,
    __nv_bfloat16* __restrict__ ctxh, __nv_bfloat16* __restrict__ ctxl)
{
    extern __shared__ float sm[];
    float* relk_s = sm;                 // [100][33]
    float* relv_s = sm + 3300;          // [100][33]
    float* kv_s   = sm + 6600;          // [64][33]
    float* sc_s   = sm + 8712;          // [8][512]
    float* qrel_s = sm + 12808;         // [8][100]
    float* mass_s = sm + 13608;         // [8][100]
    float* tmp_s  = sm + 14408;         // [8][32]

    const int tid  = threadIdx.x;
    const int w    = tid >> 5, lane = tid & 31;
    const int b    = blockIdx.x / NHEADS, h = blockIdx.x % NHEADS;
    const int q    = blockIdx.y * 8 + w;
    const float scale = 0.1767766952966369f;  // 1/sqrt(32)

    for (int i = tid; i < NREL * PH; i += 256) {
        int r = i >> 5, d = i & 31;
        relk_s[r * 33 + d] = relk[i];
        relv_s[r * 33 + d] = relv[i];
    }
    tmp_s[tid] = Q[(size_t)(b * SEQ + q) * DH + h * PH + lane];
    __syncthreads();

    float qv[PH];
    #pragma unroll
    for (int d = 0; d < PH; ++d) qv[d] = tmp_s[w * 32 + d] * scale;

    for (int r = lane; r < NREL; r += 32) {
        float a = 0.f;
        #pragma unroll
        for (int d = 0; d < PH; ++d) a = fmaf(qv[d], relk_s[r * 33 + d], a);
        qrel_s[w * 100 + r] = a;
        mass_s[w * 100 + r] = 0.f;
    }
    __syncwarp();

    const int* rmrow = rm + ((size_t)(b * SEQ + q)) * SEQ;

    // pass A: scores + running max
    float mloc = -1e30f;
    for (int kt = 0; kt < SEQ; kt += 64) {
        __syncthreads();
        for (int i = tid; i < 64 * PH; i += 256) {
            int row = i >> 5, d = i & 31;
            kv_s[row * 33 + d] = Kg[(size_t)(b * SEQ + kt + row) * DH + h * PH + d];
        }
        __syncthreads();
        #pragma unroll
        for (int c = 0; c < 64; c += 32) {
            int key = kt + c + lane;
            const float* kp = &kv_s[(c + lane) * 33];
            float s = 0.f;
            #pragma unroll
            for (int d = 0; d < PH; ++d) s = fmaf(qv[d], kp[d], s);
            s += qrel_s[w * 100 + rmrow[key]];
            sc_s[w * 512 + key] = s;
            mloc = fmaxf(mloc, s);
        }
    }
    #pragma unroll
    for (int off = 16; off > 0; off >>= 1)
        mloc = fmaxf(mloc, __shfl_xor_sync(0xffffffffu, mloc, off));

    // pass B: probs -> ctx and relation-mass histogram
    float l = 0.f;
    float ctx[PH];
    #pragma unroll
    for (int d = 0; d < PH; ++d) ctx[d] = 0.f;

    for (int kt = 0; kt < SEQ; kt += 64) {
        __syncthreads();
        for (int i = tid; i < 64 * PH; i += 256) {
            int row = i >> 5, d = i & 31;
            kv_s[row * 33 + d] = Vg[(size_t)(b * SEQ + kt + row) * DH + h * PH + d];
        }
        __syncthreads();
        #pragma unroll
        for (int c = 0; c < 64; c += 32) {
            int key = kt + c + lane;
            float p = __expf(sc_s[w * 512 + key] - mloc);
            l += p;
            atomicAdd(&mass_s[w * 100 + rmrow[key]], p);
            const float* vp = &kv_s[(c + lane) * 33];
            #pragma unroll
            for (int d = 0; d < PH; ++d) ctx[d] = fmaf(p, vp[d], ctx[d]);
        }
    }

    #pragma unroll
    for (int off = 16; off > 0; off >>= 1) {
        l += __shfl_xor_sync(0xffffffffu, l, off);
        #pragma unroll
        for (int d = 0; d < PH; ++d)
            ctx[d] += __shfl_xor_sync(0xffffffffu, ctx[d], off);
    }
    __syncwarp();

    if (lane == 0) {
        #pragma unroll
        for (int d = 0; d < PH; ++d) tmp_s[w * 32 + d] = ctx[d];
    }
    __syncwarp();

    float cd = tmp_s[w * 32 + lane];
    float racc = 0.f;
    #pragma unroll 4
    for (int r = 0; r < NREL; ++r)
        racc = fmaf(mass_s[w * 100 + r], relv_s[r * 33 + lane], racc);

    float val = (cd + racc) / l;
    __nv_bfloat16 hv = __float2bfloat16(val);
    size_t oidx = (size_t)(b * SEQ + q) * DH + h * PH + lane;
    ctxh[oidx] = hv;
    ctxl[oidx] = __float2bfloat16(val - __bfloat162float(hv));
}

// ----------------------------- launch -----------------------------------
extern "C" void kernel_launch(void* const* d_in, const int* in_sizes, int n_in,
                              void* d_out, int out_size)
{
    const float* hidden = (const float*)d_in[0];
    const float* Wq = (const float*)d_in[1];
    const float* bq = (const float*)d_in[2];
    const float* Wk = (const float*)d_in[3];
    const float* bk = (const float*)d_in[4];
    const float* Wv = (const float*)d_in[5];
    const float* bv = (const float*)d_in[6];
    const float* Wo = (const float*)d_in[7];
    const float* bo = (const float*)d_in[8];
    const float* rke = (const float*)d_in[9];
    const float* rve = (const float*)d_in[10];
    const float* W1 = (const float*)d_in[11];
    const float* b1 = (const float*)d_in[12];
    const float* W2 = (const float*)d_in[13];
    const float* b2 = (const float*)d_in[14];
    const int*   rm = (const int*)d_in[15];
    float* out = (float*)d_out;

    float *Qb, *Kb, *Vb;
    cudaGetSymbolAddress((void**)&Qb, g_Q);
    cudaGetSymbolAddress((void**)&Kb, g_K);
    cudaGetSymbolAddress((void**)&Vb, g_V);
    __nv_bfloat16 *hh, *hl, *ch, *cl, *ah, *al, *h1h, *h1l, *Wh, *Wl;
    cudaGetSymbolAddress((void**)&hh, g_hh);
    cudaGetSymbolAddress((void**)&hl, g_hl);
    cudaGetSymbolAddress((void**)&ch, g_ch);
    cudaGetSymbolAddress((void**)&cl, g_cl);
    cudaGetSymbolAddress((void**)&ah, g_ah);
    cudaGetSymbolAddress((void**)&al, g_al);
    cudaGetSymbolAddress((void**)&h1h, g_1h);
    cudaGetSymbolAddress((void**)&h1l, g_1l);
    cudaGetSymbolAddress((void**)&Wh, g_Wh);
    cudaGetSymbolAddress((void**)&Wl, g_Wl);

    cudaFuncSetAttribute(attn_v2,
        cudaFuncAttributeMaxDynamicSharedMemorySize, ATTN_SMEM);
    cudaFuncSetAttribute(hgemm_v3,
        cudaFuncAttributeMaxDynamicSharedMemorySize, GSMEM);

    // 1) all 6 weights in ONE launch
    dim3 cb(32, 8), cg(DH / 32, DH / 32, 6);
    convert_weight6<<<cg, cb>>>(Wq, Wk, Wv, Wo, W1, W2, Wh, Wl);

    // 2) split hidden
    split_act<<<(TOKS * DH) / (256 * 4), 256>>>(hidden, hh, hl);

    size_t WW = (size_t)DH * DH;
    dim3 gg(DH / 80, TOKS / 128);   // (20, 16)

    // 3-5) Q, K, V projections (fp32 out for attention)
    hgemm_v3<<<gg, 256, GSMEM>>>(hh, hl, Wh + 0 * WW, Wl + 0 * WW, bq,
                                 Qb, nullptr, nullptr, 0, 0);
    hgemm_v3<<<gg, 256, GSMEM>>>(hh, hl, Wh + 1 * WW, Wl + 1 * WW, bk,
                                 Kb, nullptr, nullptr, 0, 0);
    hgemm_v3<<<gg, 256, GSMEM>>>(hh, hl, Wh + 2 * WW, Wl + 2 * WW, bv,
                                 Vb, nullptr, nullptr, 0, 0);

    // 6) attention (ncu captures launch #6) -> ctx split
    dim3 ag(BATCH * NHEADS, SEQ / 8);  // (200, 64)
    attn_v2<<<ag, 256, ATTN_SMEM>>>(Qb, Kb, Vb, rke, rve, rm, ch, cl);

    // 7) Wo -> attn_out split
    hgemm_v3<<<gg, 256, GSMEM>>>(ch, cl, Wh + 3 * WW, Wl + 3 * WW, bo,
                                 nullptr, ah, al, 0, 1);
    // 8) W1 + gelu -> h1 split
    hgemm_v3<<<gg, 256, GSMEM>>>(ah, al, Wh + 4 * WW, Wl + 4 * WW, b1,
                                 nullptr, h1h, h1l, 1, 1);
    // 9) W2 -> final fp32 out
    hgemm_v3<<<gg, 256, GSMEM>>>(h1h, h1l, Wh + 5 * WW, Wl + 5 * WW, b2,
                                 out, nullptr, nullptr, 0, 0);
}

// round 9
// speedup vs baseline: 1.6073x; 1.0221x over previous
#include <cuda_runtime.h>
#include <cuda_bf16.h>
#include <math.h>
#include <stdint.h>

#define BATCH 4
#define SEQ   512
#define TOKS  (BATCH*SEQ)      // 2048
#define DH    1600
#define NHEADS 50
#define PH    32
#define NREL  100

// ---------------- static scratch (no allocation allowed) ----------------
__device__ float g_Q[TOKS*DH];
__device__ float g_K[TOKS*DH];
__device__ float g_V[TOKS*DH];
// bf16 hi/lo activation buffers (row-major [M][DH])
__device__ __nv_bfloat16 g_hh[TOKS*DH], g_hl[TOKS*DH];   // hidden split
__device__ __nv_bfloat16 g_ch[TOKS*DH], g_cl[TOKS*DH];   // ctx split
__device__ __nv_bfloat16 g_ah[TOKS*DH], g_al[TOKS*DH];   // attn_out split
__device__ __nv_bfloat16 g_1h[TOKS*DH], g_1l[TOKS*DH];   // h1 split
// transposed bf16 hi/lo weights: [6][N=1600][K=1600]
__device__ __nv_bfloat16 g_Wh[6][DH*DH];
__device__ __nv_bfloat16 g_Wl[6][DH*DH];

// ------------- batched weight convert: W[K][N] fp32 -> [N][K] bf16 hi/lo
__global__ __launch_bounds__(256) void convert_weight6(
    const float* W0, const float* W1, const float* W2,
    const float* W3, const float* W4, const float* W5,
    __nv_bfloat16* __restrict__ hi_base, __nv_bfloat16* __restrict__ lo_base)
{
    __shared__ float t[32][33];
    const int wi = blockIdx.z;
    const float* W = (wi == 0) ? W0 : (wi == 1) ? W1 : (wi == 2) ? W2 :
                     (wi == 3) ? W3 : (wi == 4) ? W4 : W5;
    __nv_bfloat16* hi = hi_base + (size_t)wi * DH * DH;
    __nv_bfloat16* lo = lo_base + (size_t)wi * DH * DH;
    const int n0 = blockIdx.x * 32, k0 = blockIdx.y * 32;
    const int tx = threadIdx.x, ty = threadIdx.y;   // (32,8)
    #pragma unroll
    for (int j = 0; j < 32; j += 8)
        t[ty + j][tx] = W[(size_t)(k0 + ty + j) * DH + n0 + tx];
    __syncthreads();
    #pragma unroll
    for (int j = 0; j < 32; j += 8) {
        float v = t[tx][ty + j];
        __nv_bfloat16 h = __float2bfloat16(v);
        __nv_bfloat16 l = __float2bfloat16(v - __bfloat162float(h));
        size_t o = (size_t)(n0 + ty + j) * DH + k0 + tx;
        hi[o] = h; lo[o] = l;
    }
}

// ------------- activation split: fp32 -> bf16 hi/lo ---------------------
__global__ __launch_bounds__(256) void split_act(
    const float* __restrict__ x,
    __nv_bfloat16* __restrict__ hi, __nv_bfloat16* __restrict__ lo)
{
    size_t i = ((size_t)blockIdx.x * 256 + threadIdx.x) * 4;
    float4 v = *(const float4*)(x + i);
    __nv_bfloat16 hx = __float2bfloat16(v.x), hy = __float2bfloat16(v.y);
    __nv_bfloat16 hz = __float2bfloat16(v.z), hw = __float2bfloat16(v.w);
    __nv_bfloat162 h01; h01.x = hx; h01.y = hy;
    __nv_bfloat162 h23; h23.x = hz; h23.y = hw;
    *(__nv_bfloat162*)(hi + i)     = h01;
    *(__nv_bfloat162*)(hi + i + 2) = h23;
    __nv_bfloat162 l01, l23;
    l01.x = __float2bfloat16(v.x - __bfloat162float(hx));
    l01.y = __float2bfloat16(v.y - __bfloat162float(hy));
    l23.x = __float2bfloat16(v.z - __bfloat162float(hz));
    l23.y = __float2bfloat16(v.w - __bfloat162float(hw));
    *(__nv_bfloat162*)(lo + i)     = l01;
    *(__nv_bfloat162*)(lo + i + 2) = l23;
}

// ------------- bf16x3 tensor-core GEMM, 3-stage cp.async ----------------
// C = (Ah+Al) @ (Bh+Bl)^T + bias;  D = Ah*Bh + Ah*Bl + Al*Bh (fp32 acc)
// BM=128 BN=80 BK=32, 256 thr = 8 warps (4m x 2n), warp tile 32x40.
// stage words: Ahi 2560 | Alo 2560 | Bhi 1600 | Blo 1600 = 8320
#define GSTAGE 8320
#define NSTG   3
#define GSMEM  (NSTG * GSTAGE * 4)   // 99840 B

__device__ __forceinline__ void mma16816(float* c, const uint32_t* a,
                                         uint32_t b0, uint32_t b1) {
    asm volatile(
        "mma.sync.aligned.m16n8k16.row.col.f32.bf16.bf16.f32 "
        "{%0,%1,%2,%3}, {%4,%5,%6,%7}, {%8,%9}, {%0,%1,%2,%3};"
        : "+f"(c[0]), "+f"(c[1]), "+f"(c[2]), "+f"(c[3])
        : "r"(a[0]), "r"(a[1]), "r"(a[2]), "r"(a[3]), "r"(b0), "r"(b1));
}
__device__ __forceinline__ void cpasync16(uint32_t dst, const void* src) {
    asm volatile("cp.async.cg.shared.global [%0], [%1], 16;"
                 :: "r"(dst), "l"(src));
}

__global__ __launch_bounds__(256, 2) void hgemm_v3(
    const __nv_bfloat16* __restrict__ Ah, const __nv_bfloat16* __restrict__ Al,
    const __nv_bfloat16* __restrict__ Bh, const __nv_bfloat16* __restrict__ Bl,
    const float* __restrict__ bias,
    float* __restrict__ Cf,
    __nv_bfloat16* __restrict__ Ch, __nv_bfloat16* __restrict__ Cl,
    int act, int mode)   // mode 0: fp32 out; mode 1: split bf16 out
{
    extern __shared__ uint32_t smw[];
    const uint32_t sm0 = (uint32_t)__cvta_generic_to_shared(smw);

    const int tid  = threadIdx.x;
    const int lane = tid & 31, warp = tid >> 5;
    const int wm = warp >> 1, wn = warp & 1;
    const int g = lane >> 2, t4 = lane & 3;
    const int bm = blockIdx.y * 128, bn = blockIdx.x * 80;

    float acc[2][5][4];
    #pragma unroll
    for (int mt = 0; mt < 2; ++mt)
        #pragma unroll
        for (int nt = 0; nt < 5; ++nt)
            #pragma unroll
            for (int i = 0; i < 4; ++i) acc[mt][nt][i] = 0.f;

    // ---- tile loader (cp.async, 16B = 8 bf16 chunks) ----
    auto load_tile = [&](int stage, int kk) {
        uint32_t sb = sm0 + stage * GSTAGE * 4;
        // A: 1024 chunks (hi 512 + lo 512), 4 per thread
        #pragma unroll
        for (int it = 0; it < 4; ++it) {
            int idx = tid + it * 256;
            int hl = idx >> 9;
            int r  = (idx >> 2) & 127;
            int c  = idx & 3;
            const __nv_bfloat16* src =
                (hl ? Al : Ah) + (size_t)(bm + r) * DH + kk + c * 8;
            cpasync16(sb + (hl * 2560 + r * 20 + c * 4) * 4, src);
        }
        // B: 640 chunks (hi 320 + lo 320)
        for (int idx = tid; idx < 640; idx += 256) {
            int hl = idx >= 320;
            int j  = idx - hl * 320;
            int r  = j >> 2, c = j & 3;
            const __nv_bfloat16* src =
                (hl ? Bl : Bh) + (size_t)(bn + r) * DH + kk + c * 8;
            cpasync16(sb + (5120 + hl * 1600 + r * 20 + c * 4) * 4, src);
        }
        asm volatile("cp.async.commit_group;");
    };

    const int NT = DH / 32;   // 50
    load_tile(0, 0);
    load_tile(1, 32);

    for (int t = 0; t < NT; ++t) {
        int cur = t % NSTG;
        if (t + 1 < NT) asm volatile("cp.async.wait_group 1;");
        else            asm volatile("cp.async.wait_group 0;");
        __syncthreads();

        // prefetch t+2 into stage (t+2)%3 (held tile t-1; all threads are
        // past its compute thanks to the barrier above)
        if (t + 2 < NT) load_tile((t + 2) % NSTG, (t + 2) * 32);

        const uint32_t* S  = smw + cur * GSTAGE;
        const uint32_t* A0 = S;           // A hi
        const uint32_t* A1 = S + 2560;    // A lo
        const uint32_t* B0 = S + 5120;    // B hi
        const uint32_t* B1 = S + 6720;    // B lo

        #pragma unroll
        for (int ks = 0; ks < 16; ks += 8) {   // two k16 halves of BK=32
            uint32_t ah[2][4], al[2][4];
            #pragma unroll
            for (int mt = 0; mt < 2; ++mt) {
                int base = (wm * 32 + mt * 16 + g) * 20 + ks + t4;
                ah[mt][0] = A0[base];     ah[mt][1] = A0[base + 160];
                ah[mt][2] = A0[base + 4]; ah[mt][3] = A0[base + 164];
                al[mt][0] = A1[base];     al[mt][1] = A1[base + 160];
                al[mt][2] = A1[base + 4]; al[mt][3] = A1[base + 164];
            }
            #pragma unroll
            for (int nt = 0; nt < 5; ++nt) {
                int bb = (wn * 40 + nt * 8 + g) * 20 + ks + t4;
                uint32_t bh0 = B0[bb], bh1 = B0[bb + 4];
                uint32_t bl0 = B1[bb], bl1 = B1[bb + 4];
                #pragma unroll
                for (int mt = 0; mt < 2; ++mt) {
                    mma16816(acc[mt][nt], ah[mt], bh0, bh1);
                    mma16816(acc[mt][nt], ah[mt], bl0, bl1);
                    mma16816(acc[mt][nt], al[mt], bh0, bh1);
                }
            }
        }
    }

    // ---- epilogue (warp tile 32x40: cols wn*40 + nt*8) ----
    #pragma unroll
    for (int mt = 0; mt < 2; ++mt) {
        #pragma unroll
        for (int nt = 0; nt < 5; ++nt) {
            int r0 = bm + wm * 32 + mt * 16 + g;
            int c0 = bn + wn * 40 + nt * 8 + t4 * 2;
            float b0v = bias[c0], b1v = bias[c0 + 1];
            float x0 = acc[mt][nt][0] + b0v, x1 = acc[mt][nt][1] + b1v;
            float x2 = acc[mt][nt][2] + b0v, x3 = acc[mt][nt][3] + b1v;
            if (act) {
                x0 = 0.5f * x0 * (1.f + erff(x0 * 0.70710678118654752f));
                x1 = 0.5f * x1 * (1.f + erff(x1 * 0.70710678118654752f));
                x2 = 0.5f * x2 * (1.f + erff(x2 * 0.70710678118654752f));
                x3 = 0.5f * x3 * (1.f + erff(x3 * 0.70710678118654752f));
            }
            if (mode == 0) {
                *(float2*)(Cf + (size_t)r0 * DH + c0)       = make_float2(x0, x1);
                *(float2*)(Cf + (size_t)(r0 + 8) * DH + c0) = make_float2(x2, x3);
            } else {
                __nv_bfloat162 h01, h23, l01, l23;
                h01.x = __float2bfloat16(x0); h01.y = __float2bfloat16(x1);
                h23.x = __float2bfloat16(x2); h23.y = __float2bfloat16(x3);
                l01.x = __float2bfloat16(x0 - __bfloat162float(h01.x));
                l01.y = __float2bfloat16(x1 - __bfloat162float(h01.y));
                l23.x = __float2bfloat16(x2 - __bfloat162float(h23.x));
                l23.y = __float2bfloat16(x3 - __bfloat162float(h23.y));
                *(__nv_bfloat162*)(Ch + (size_t)r0 * DH + c0)       = h01;
                *(__nv_bfloat162*)(Ch + (size_t)(r0 + 8) * DH + c0) = h23;
                *(__nv_bfloat162*)(Cl + (size_t)r0 * DH + c0)       = l01;
                *(__nv_bfloat162*)(Cl + (size_t)(r0 + 8) * DH + c0) = l23;
            }
        }
    }
}

// ------------- attention v3: warp-per-query, scores in registers --------
// smem floats: relk 3300 | relv 3300 | kv 2304 (64x36) | qrel 800 |
//              mass 800 | tmp 256 = 10760 floats = 43040 B
#define ATTN_SMEM (10760 * 4)

__global__ __launch_bounds__(256, 2) void attn_v3(
    const float* __restrict__ Q, const float* __restrict__ Kg,
    const float* __restrict__ Vg,
    const float* __restrict__ relk, const float* __restrict__ relv,
    const int* __restrict__ rm,
    __nv_bfloat16* __restrict__ ctxh, __nv_bfloat16* __restrict__ ctxl)
{
    extern __shared__ float sm[];
    float* relk_s = sm;                 // [100][33]
    float* relv_s = sm + 3300;          // [100][33]
    float* kv_s   = sm + 6600;          // [64][36]  (16B-aligned rows)
    float* qrel_s = sm + 8904;          // [8][100]
    float* mass_s = sm + 9704;          // [8][100]
    float* tmp_s  = sm + 10504;         // [8][32]

    const int tid  = threadIdx.x;
    const int w    = tid >> 5, lane = tid & 31;
    const int b    = blockIdx.x / NHEADS, h = blockIdx.x % NHEADS;
    const int q    = blockIdx.y * 8 + w;
    const float scale = 0.1767766952966369f;  // 1/sqrt(32)

    for (int i = tid; i < NREL * PH; i += 256) {
        int r = i >> 5, d = i & 31;
        relk_s[r * 33 + d] = relk[i];
        relv_s[r * 33 + d] = relv[i];
    }
    tmp_s[tid] = Q[(size_t)(b * SEQ + q) * DH + h * PH + lane];
    __syncthreads();

    float qv[PH];
    #pragma unroll
    for (int d = 0; d < PH; ++d) qv[d] = tmp_s[w * 32 + d] * scale;

    for (int r = lane; r < NREL; r += 32) {
        float a0 = 0.f, a1 = 0.f, a2 = 0.f, a3 = 0.f;
        #pragma unroll
        for (int d = 0; d < PH; d += 4) {
            a0 = fmaf(qv[d + 0], relk_s[r * 33 + d + 0], a0);
            a1 = fmaf(qv[d + 1], relk_s[r * 33 + d + 1], a1);
            a2 = fmaf(qv[d + 2], relk_s[r * 33 + d + 2], a2);
            a3 = fmaf(qv[d + 3], relk_s[r * 33 + d + 3], a3);
        }
        qrel_s[w * 100 + r] = (a0 + a1) + (a2 + a3);
        mass_s[w * 100 + r] = 0.f;
    }
    __syncwarp();

    const int* rmrow = rm + ((size_t)(b * SEQ + q)) * SEQ;

    // ---- pass A: scores (kept in 16 registers) + running max ----
    float sreg[16];
    float mloc = -1e30f;
    #pragma unroll
    for (int ti = 0; ti < 8; ++ti) {
        __syncthreads();
        for (int i = tid; i < 512; i += 256) {       // 64x32 floats as float4
            int row = i >> 3, c4 = i & 7;
            *(float4*)&kv_s[row * 36 + c4 * 4] =
                *(const float4*)(Kg + (size_t)(b * SEQ + ti * 64 + row) * DH
                                 + h * PH + c4 * 4);
        }
        __syncthreads();
        #pragma unroll
        for (int cc = 0; cc < 2; ++cc) {
            const int ch  = ti * 2 + cc;
            const int key = ti * 64 + cc * 32 + lane;
            const float4* kp = (const float4*)&kv_s[(cc * 32 + lane) * 36];
            float s0 = 0.f, s1 = 0.f, s2 = 0.f, s3 = 0.f;
            #pragma unroll
            for (int j = 0; j < 8; ++j) {
                float4 kvv = kp[j];
                s0 = fmaf(qv[j * 4 + 0], kvv.x, s0);
                s1 = fmaf(qv[j * 4 + 1], kvv.y, s1);
                s2 = fmaf(qv[j * 4 + 2], kvv.z, s2);
                s3 = fmaf(qv[j * 4 + 3], kvv.w, s3);
            }
            float s = (s0 + s1) + (s2 + s3) + qrel_s[w * 100 + rmrow[key]];
            sreg[ch] = s;
            mloc = fmaxf(mloc, s);
        }
    }
    #pragma unroll
    for (int off = 16; off > 0; off >>= 1)
        mloc = fmaxf(mloc, __shfl_xor_sync(0xffffffffu, mloc, off));

    // ---- pass B: probs -> ctx and relation-mass histogram ----
    float l = 0.f;
    float ctx[PH];
    #pragma unroll
    for (int d = 0; d < PH; ++d) ctx[d] = 0.f;

    #pragma unroll
    for (int ti = 0; ti < 8; ++ti) {
        __syncthreads();
        for (int i = tid; i < 512; i += 256) {
            int row = i >> 3, c4 = i & 7;
            *(float4*)&kv_s[row * 36 + c4 * 4] =
                *(const float4*)(Vg + (size_t)(b * SEQ + ti * 64 + row) * DH
                                 + h * PH + c4 * 4);
        }
        __syncthreads();
        #pragma unroll
        for (int cc = 0; cc < 2; ++cc) {
            const int ch  = ti * 2 + cc;
            const int key = ti * 64 + cc * 32 + lane;
            float p = __expf(sreg[ch] - mloc);
            l += p;
            atomicAdd(&mass_s[w * 100 + rmrow[key]], p);
            const float4* vp = (const float4*)&kv_s[(cc * 32 + lane) * 36];
            #pragma unroll
            for (int j = 0; j < 8; ++j) {
                float4 vv = vp[j];
                ctx[j * 4 + 0] = fmaf(p, vv.x, ctx[j * 4 + 0]);
                ctx[j * 4 + 1] = fmaf(p, vv.y, ctx[j * 4 + 1]);
                ctx[j * 4 + 2] = fmaf(p, vv.z, ctx[j * 4 + 2]);
                ctx[j * 4 + 3] = fmaf(p, vv.w, ctx[j * 4 + 3]);
            }
        }
    }

    #pragma unroll
    for (int off = 16; off > 0; off >>= 1) {
        l += __shfl_xor_sync(0xffffffffu, l, off);
        #pragma unroll
        for (int d = 0; d < PH; ++d)
            ctx[d] += __shfl_xor_sync(0xffffffffu, ctx[d], off);
    }
    __syncwarp();

    if (lane == 0) {
        #pragma unroll
        for (int d = 0; d < PH; ++d) tmp_s[w * 32 + d] = ctx[d];
    }
    __syncwarp();

    // lane d finalizes dim d: (ctx[d] + sum_r mass[r]*rel_v[r][d]) / l
    float cd = tmp_s[w * 32 + lane];
    float racc = 0.f;
    #pragma unroll 4
    for (int r = 0; r < NREL; ++r)
        racc = fmaf(mass_s[w * 100 + r], relv_s[r * 33 + lane], racc);

    float val = (cd + racc) / l;
    __nv_bfloat16 hv = __float2bfloat16(val);
    size_t oidx = (size_t)(b * SEQ + q) * DH + h * PH + lane;
    ctxh[oidx] = hv;
    ctxl[oidx] = __float2bfloat16(val - __bfloat162float(hv));
}

// ----------------------------- launch -----------------------------------
extern "C" void kernel_launch(void* const* d_in, const int* in_sizes, int n_in,
                              void* d_out, int out_size)
{
    const float* hidden = (const float*)d_in[0];
    const float* Wq = (const float*)d_in[1];
    const float* bq = (const float*)d_in[2];
    const float* Wk = (const float*)d_in[3];
    const float* bk = (const float*)d_in[4];
    const float* Wv = (const float*)d_in[5];
    const float* bv = (const float*)d_in[6];
    const float* Wo = (const float*)d_in[7];
    const float* bo = (const float*)d_in[8];
    const float* rke = (const float*)d_in[9];
    const float* rve = (const float*)d_in[10];
    const float* W1 = (const float*)d_in[11];
    const float* b1 = (const float*)d_in[12];
    const float* W2 = (const float*)d_in[13];
    const float* b2 = (const float*)d_in[14];
    const int*   rm = (const int*)d_in[15];
    float* out = (float*)d_out;

    float *Qb, *Kb, *Vb;
    cudaGetSymbolAddress((void**)&Qb, g_Q);
    cudaGetSymbolAddress((void**)&Kb, g_K);
    cudaGetSymbolAddress((void**)&Vb, g_V);
    __nv_bfloat16 *hh, *hl, *ch, *cl, *ah, *al, *h1h, *h1l, *Wh, *Wl;
    cudaGetSymbolAddress((void**)&hh, g_hh);
    cudaGetSymbolAddress((void**)&hl, g_hl);
    cudaGetSymbolAddress((void**)&ch, g_ch);
    cudaGetSymbolAddress((void**)&cl, g_cl);
    cudaGetSymbolAddress((void**)&ah, g_ah);
    cudaGetSymbolAddress((void**)&al, g_al);
    cudaGetSymbolAddress((void**)&h1h, g_1h);
    cudaGetSymbolAddress((void**)&h1l, g_1l);
    cudaGetSymbolAddress((void**)&Wh, g_Wh);
    cudaGetSymbolAddress((void**)&Wl, g_Wl);

    cudaFuncSetAttribute(attn_v3,
        cudaFuncAttributeMaxDynamicSharedMemorySize, ATTN_SMEM);
    cudaFuncSetAttribute(hgemm_v3,
        cudaFuncAttributeMaxDynamicSharedMemorySize, GSMEM);

    // 1) all 6 weights in ONE launch
    dim3 cb(32, 8), cg(DH / 32, DH / 32, 6);
    convert_weight6<<<cg, cb>>>(Wq, Wk, Wv, Wo, W1, W2, Wh, Wl);

    // 2) split hidden
    split_act<<<(TOKS * DH) / (256 * 4), 256>>>(hidden, hh, hl);

    size_t WW = (size_t)DH * DH;
    dim3 gg(DH / 80, TOKS / 128);   // (20, 16)

    // 3-5) Q, K, V projections (fp32 out for attention)
    hgemm_v3<<<gg, 256, GSMEM>>>(hh, hl, Wh + 0 * WW, Wl + 0 * WW, bq,
                                 Qb, nullptr, nullptr, 0, 0);
    hgemm_v3<<<gg, 256, GSMEM>>>(hh, hl, Wh + 1 * WW, Wl + 1 * WW, bk,
                                 Kb, nullptr, nullptr, 0, 0);
    hgemm_v3<<<gg, 256, GSMEM>>>(hh, hl, Wh + 2 * WW, Wl + 2 * WW, bv,
                                 Vb, nullptr, nullptr, 0, 0);

    // 6) attention (ncu captures launch #6) -> ctx split
    dim3 ag(BATCH * NHEADS, SEQ / 8);  // (200, 64)
    attn_v3<<<ag, 256, ATTN_SMEM>>>(Qb, Kb, Vb, rke, rve, rm, ch, cl);

    // 7) Wo -> attn_out split
    hgemm_v3<<<gg, 256, GSMEM>>>(ch, cl, Wh + 3 * WW, Wl + 3 * WW, bo,
                                 nullptr, ah, al, 0, 1);
    // 8) W1 + gelu -> h1 split
    hgemm_v3<<<gg, 256, GSMEM>>>(ah, al, Wh + 4 * WW, Wl + 4 * WW, b1,
                                 nullptr, h1h, h1l, 1, 1);
    // 9) W2 -> final fp32 out
    hgemm_v3<<<gg, 256, GSMEM>>>(h1h, h1l, Wh + 5 * WW, Wl + 5 * WW, b2,
                                 out, nullptr, nullptr, 0, 0);
}

// round 11
// speedup vs baseline: 1.7325x; 1.0778x over previous
#include <cuda_runtime.h>
#include <cuda_bf16.h>
#include <math.h>
#include <stdint.h>

#define BATCH 4
#define SEQ   512
#define TOKS  (BATCH*SEQ)      // 2048
#define DH    1600
#define NHEADS 50
#define PH    32
#define NREL  100

// ---------------- static scratch (no allocation allowed) ----------------
__device__ float g_Q[TOKS*DH];
__device__ float g_K[TOKS*DH];
__device__ float g_V[TOKS*DH];
__device__ __nv_bfloat16 g_hh[TOKS*DH], g_hl[TOKS*DH];   // hidden split
__device__ __nv_bfloat16 g_ch[TOKS*DH], g_cl[TOKS*DH];   // ctx split
__device__ __nv_bfloat16 g_ah[TOKS*DH], g_al[TOKS*DH];   // attn_out split
__device__ __nv_bfloat16 g_1h[TOKS*DH], g_1l[TOKS*DH];   // h1 split
__device__ __nv_bfloat16 g_Wh[6][DH*DH];
__device__ __nv_bfloat16 g_Wl[6][DH*DH];

// ------------- batched weight convert: W[K][N] fp32 -> [N][K] bf16 hi/lo
__global__ __launch_bounds__(256) void convert_weight6(
    const float* W0, const float* W1, const float* W2,
    const float* W3, const float* W4, const float* W5,
    __nv_bfloat16* __restrict__ hi_base, __nv_bfloat16* __restrict__ lo_base)
{
    __shared__ float t[32][33];
    const int wi = blockIdx.z;
    const float* W = (wi == 0) ? W0 : (wi == 1) ? W1 : (wi == 2) ? W2 :
                     (wi == 3) ? W3 : (wi == 4) ? W4 : W5;
    __nv_bfloat16* hi = hi_base + (size_t)wi * DH * DH;
    __nv_bfloat16* lo = lo_base + (size_t)wi * DH * DH;
    const int n0 = blockIdx.x * 32, k0 = blockIdx.y * 32;
    const int tx = threadIdx.x, ty = threadIdx.y;   // (32,8)
    #pragma unroll
    for (int j = 0; j < 32; j += 8)
        t[ty + j][tx] = W[(size_t)(k0 + ty + j) * DH + n0 + tx];
    __syncthreads();
    #pragma unroll
    for (int j = 0; j < 32; j += 8) {
        float v = t[tx][ty + j];
        __nv_bfloat16 h = __float2bfloat16(v);
        __nv_bfloat16 l = __float2bfloat16(v - __bfloat162float(h));
        size_t o = (size_t)(n0 + ty + j) * DH + k0 + tx;
        hi[o] = h; lo[o] = l;
    }
}

// ------------- activation split: fp32 -> bf16 hi/lo ---------------------
__global__ __launch_bounds__(256) void split_act(
    const float* __restrict__ x,
    __nv_bfloat16* __restrict__ hi, __nv_bfloat16* __restrict__ lo)
{
    size_t i = ((size_t)blockIdx.x * 256 + threadIdx.x) * 4;
    float4 v = *(const float4*)(x + i);
    __nv_bfloat16 hx = __float2bfloat16(v.x), hy = __float2bfloat16(v.y);
    __nv_bfloat16 hz = __float2bfloat16(v.z), hw = __float2bfloat16(v.w);
    __nv_bfloat162 h01; h01.x = hx; h01.y = hy;
    __nv_bfloat162 h23; h23.x = hz; h23.y = hw;
    *(__nv_bfloat162*)(hi + i)     = h01;
    *(__nv_bfloat162*)(hi + i + 2) = h23;
    __nv_bfloat162 l01, l23;
    l01.x = __float2bfloat16(v.x - __bfloat162float(hx));
    l01.y = __float2bfloat16(v.y - __bfloat162float(hy));
    l23.x = __float2bfloat16(v.z - __bfloat162float(hz));
    l23.y = __float2bfloat16(v.w - __bfloat162float(hw));
    *(__nv_bfloat162*)(lo + i)     = l01;
    *(__nv_bfloat162*)(lo + i + 2) = l23;
}

// ------------- bf16x3 tensor-core GEMM, ldmatrix + 2-stage cp.async -----
// BM=128 BN=80 BK=32, 256 thr = 8 warps (4m x 2n), warp tile 32x40.
// stage words: Ahi 2560 | Alo 2560 | Bhi 1600 | Blo 1600 = 8320
#define GSTAGE 8320
#define GSMEM  (2 * GSTAGE * 4)

__device__ __forceinline__ void mma16816(float* c, const uint32_t* a,
                                         uint32_t b0, uint32_t b1) {
    asm volatile(
        "mma.sync.aligned.m16n8k16.row.col.f32.bf16.bf16.f32 "
        "{%0,%1,%2,%3}, {%4,%5,%6,%7}, {%8,%9}, {%0,%1,%2,%3};"
        : "+f"(c[0]), "+f"(c[1]), "+f"(c[2]), "+f"(c[3])
        : "r"(a[0]), "r"(a[1]), "r"(a[2]), "r"(a[3]), "r"(b0), "r"(b1));
}
__device__ __forceinline__ void cpasync16(uint32_t dst, const void* src) {
    asm volatile("cp.async.cg.shared.global [%0], [%1], 16;"
                 :: "r"(dst), "l"(src));
}
__device__ __forceinline__ void ldsm4(uint32_t* r, uint32_t a) {
    asm volatile("ldmatrix.sync.aligned.m8n8.x4.shared.b16 {%0,%1,%2,%3}, [%4];"
                 : "=r"(r[0]), "=r"(r[1]), "=r"(r[2]), "=r"(r[3]) : "r"(a));
}

__global__ __launch_bounds__(256, 2) void hgemm_v4(
    const __nv_bfloat16* __restrict__ Ah, const __nv_bfloat16* __restrict__ Al,
    const __nv_bfloat16* __restrict__ Bh, const __nv_bfloat16* __restrict__ Bl,
    const float* __restrict__ bias,
    float* __restrict__ Cf,
    __nv_bfloat16* __restrict__ Ch, __nv_bfloat16* __restrict__ Cl,
    int act, int mode)   // mode 0: fp32 out; mode 1: split bf16 out
{
    extern __shared__ uint32_t smw[];
    const uint32_t sm0 = (uint32_t)__cvta_generic_to_shared(smw);

    const int tid  = threadIdx.x;
    const int lane = tid & 31, warp = tid >> 5;
    const int wm = warp >> 1, wn = warp & 1;
    const int g = lane >> 2, t4 = lane & 3;
    const int bm = blockIdx.y * 128, bn = blockIdx.x * 80;

    float acc[2][5][4];
    #pragma unroll
    for (int mt = 0; mt < 2; ++mt)
        #pragma unroll
        for (int nt = 0; nt < 5; ++nt)
            #pragma unroll
            for (int i = 0; i < 4; ++i) acc[mt][nt][i] = 0.f;

    // ldmatrix per-lane byte offsets within a stage
    const uint32_t aRow = wm * 32 + (lane & 7) + 8 * ((lane >> 3) & 1);
    const uint32_t aOff = (aRow * 20 + 4 * (lane >> 4)) * 4;
    const uint32_t bOff = (5120 + (wn * 40 + (lane & 7)) * 20 + 4 * (lane >> 3)) * 4;

    auto load_tile = [&](int stage, int kk) {
        uint32_t sb = sm0 + stage * GSTAGE * 4;
        #pragma unroll
        for (int it = 0; it < 4; ++it) {         // A: 1024 16B chunks
            int idx = tid + it * 256;
            int hl = idx >> 9;
            int r  = (idx >> 2) & 127;
            int c  = idx & 3;
            const __nv_bfloat16* src =
                (hl ? Al : Ah) + (size_t)(bm + r) * DH + kk + c * 8;
            cpasync16(sb + (hl * 2560 + r * 20 + c * 4) * 4, src);
        }
        for (int idx = tid; idx < 640; idx += 256) {  // B: 640 chunks
            int hl = idx >= 320;
            int j  = idx - hl * 320;
            int r  = j >> 2, c = j & 3;
            const __nv_bfloat16* src =
                (hl ? Bl : Bh) + (size_t)(bn + r) * DH + kk + c * 8;
            cpasync16(sb + (5120 + hl * 1600 + r * 20 + c * 4) * 4, src);
        }
        asm volatile("cp.async.commit_group;");
    };

    const int NT = DH / 32;   // 50
    load_tile(0, 0);

    for (int t = 0; t < NT; ++t) {
        int cur = t & 1;
        if (t + 1 < NT) {
            load_tile(cur ^ 1, (t + 1) * 32);
            asm volatile("cp.async.wait_group 1;");
        } else {
            asm volatile("cp.async.wait_group 0;");
        }
        __syncthreads();

        const uint32_t sb = sm0 + cur * GSTAGE * 4;

        uint32_t bh[5][4], bl[5][4];
        #pragma unroll
        for (int nt = 0; nt < 5; ++nt) {
            ldsm4(bh[nt], sb + bOff + nt * (8 * 20 * 4));
            ldsm4(bl[nt], sb + bOff + nt * (8 * 20 * 4) + 1600 * 4);
        }

        #pragma unroll
        for (int kh = 0; kh < 2; ++kh) {          // two k16 halves
            const int ks = kh * 8, o = kh * 2;
            uint32_t ah[2][4], al[2][4];
            #pragma unroll
            for (int mt = 0; mt < 2; ++mt) {
                uint32_t a = sb + aOff + (mt * 16 * 20 + ks) * 4;
                ldsm4(ah[mt], a);
                ldsm4(al[mt], a + 2560 * 4);
            }
            #pragma unroll
            for (int nt = 0; nt < 5; ++nt) {
                #pragma unroll
                for (int mt = 0; mt < 2; ++mt) {
                    mma16816(acc[mt][nt], ah[mt], bh[nt][o], bh[nt][o + 1]);
                    mma16816(acc[mt][nt], ah[mt], bl[nt][o], bl[nt][o + 1]);
                    mma16816(acc[mt][nt], al[mt], bh[nt][o], bh[nt][o + 1]);
                }
            }
        }
        __syncthreads();
    }

    // ---- epilogue ----
    #pragma unroll
    for (int mt = 0; mt < 2; ++mt) {
        #pragma unroll
        for (int nt = 0; nt < 5; ++nt) {
            int r0 = bm + wm * 32 + mt * 16 + g;
            int c0 = bn + wn * 40 + nt * 8 + t4 * 2;
            float b0v = bias[c0], b1v = bias[c0 + 1];
            float x0 = acc[mt][nt][0] + b0v, x1 = acc[mt][nt][1] + b1v;
            float x2 = acc[mt][nt][2] + b0v, x3 = acc[mt][nt][3] + b1v;
            if (act) {
                x0 = 0.5f * x0 * (1.f + erff(x0 * 0.70710678118654752f));
                x1 = 0.5f * x1 * (1.f + erff(x1 * 0.70710678118654752f));
                x2 = 0.5f * x2 * (1.f + erff(x2 * 0.70710678118654752f));
                x3 = 0.5f * x3 * (1.f + erff(x3 * 0.70710678118654752f));
            }
            if (mode == 0) {
                *(float2*)(Cf + (size_t)r0 * DH + c0)       = make_float2(x0, x1);
                *(float2*)(Cf + (size_t)(r0 + 8) * DH + c0) = make_float2(x2, x3);
            } else {
                __nv_bfloat162 h01, h23, l01, l23;
                h01.x = __float2bfloat16(x0); h01.y = __float2bfloat16(x1);
                h23.x = __float2bfloat16(x2); h23.y = __float2bfloat16(x3);
                l01.x = __float2bfloat16(x0 - __bfloat162float(h01.x));
                l01.y = __float2bfloat16(x1 - __bfloat162float(h01.y));
                l23.x = __float2bfloat16(x2 - __bfloat162float(h23.x));
                l23.y = __float2bfloat16(x3 - __bfloat162float(h23.y));
                *(__nv_bfloat162*)(Ch + (size_t)r0 * DH + c0)       = h01;
                *(__nv_bfloat162*)(Ch + (size_t)(r0 + 8) * DH + c0) = h23;
                *(__nv_bfloat162*)(Cl + (size_t)r0 * DH + c0)       = l01;
                *(__nv_bfloat162*)(Cl + (size_t)(r0 + 8) * DH + c0) = l23;
            }
        }
    }
}

// ------------- attention v4b: single-pass online softmax ----------------
// FIX vs R9: on max update, rescale the per-warp relation-mass histogram
// by alpha too (it holds exp(s - m) terms; m changed). Warp-uniform branch,
// lanes cover distinct bins, __syncwarp before subsequent atomicAdds.
#define ATTN_SMEM (19016 * 4)

__global__ __launch_bounds__(512) void attn_v4(
    const float* __restrict__ Q, const float* __restrict__ Kg,
    const float* __restrict__ Vg,
    const float* __restrict__ relk, const float* __restrict__ relv,
    const int* __restrict__ rm,
    __nv_bfloat16* __restrict__ ctxh, __nv_bfloat16* __restrict__ ctxl)
{
    extern __shared__ float sm[];
    float* relk_s = sm;                 // [100][33]
    float* relv_s = sm + 3300;          // [100][33]
    float* kv_s   = sm + 6600;          // [2][64][68]
    float* qrel_s = sm + 15304;         // [16][100]
    float* mass_s = sm + 16904;         // [16][100]
    float* tmp_s  = sm + 18504;         // [16][32]
    const uint32_t kv0 = (uint32_t)__cvta_generic_to_shared(kv_s);

    const int tid  = threadIdx.x;
    const int w    = tid >> 5, lane = tid & 31;
    const int b    = blockIdx.x / NHEADS, h = blockIdx.x % NHEADS;
    const int q    = blockIdx.y * 16 + w;
    const float scale = 0.1767766952966369f;  // 1/sqrt(32)

    for (int i = tid; i < NREL * PH; i += 512) {
        int r = i >> 5, d = i & 31;
        relk_s[r * 33 + d] = relk[i];
        relv_s[r * 33 + d] = relv[i];
    }
    tmp_s[tid] = Q[(size_t)(b * SEQ + q) * DH + h * PH + lane];
    __syncthreads();

    float qv[PH];
    #pragma unroll
    for (int d = 0; d < PH; ++d) qv[d] = tmp_s[w * 32 + d] * scale;

    for (int r = lane; r < NREL; r += 32) {
        float a0 = 0.f, a1 = 0.f, a2 = 0.f, a3 = 0.f;
        #pragma unroll
        for (int d = 0; d < PH; d += 4) {
            a0 = fmaf(qv[d + 0], relk_s[r * 33 + d + 0], a0);
            a1 = fmaf(qv[d + 1], relk_s[r * 33 + d + 1], a1);
            a2 = fmaf(qv[d + 2], relk_s[r * 33 + d + 2], a2);
            a3 = fmaf(qv[d + 3], relk_s[r * 33 + d + 3], a3);
        }
        qrel_s[w * 100 + r] = (a0 + a1) + (a2 + a3);
        mass_s[w * 100 + r] = 0.f;
    }
    __syncwarp();

    const int* rmrow = rm + ((size_t)(b * SEQ + q)) * SEQ;

    auto load_tile = [&](int stage, int ti) {
        #pragma unroll
        for (int it = 0; it < 2; ++it) {
            int idx = tid + it * 512;
            int half = idx >> 9;                 // 0 = K, 1 = V
            int j = idx & 511;
            int r = j >> 3, c4 = j & 7;
            const float* src = (half ? Vg : Kg) +
                (size_t)(b * SEQ + ti * 64 + r) * DH + h * PH + c4 * 4;
            cpasync16(kv0 + (stage * 4352 + r * 68 + half * 36 + c4 * 4) * 4, src);
        }
        asm volatile("cp.async.commit_group;");
    };

    load_tile(0, 0);

    float m = -1e30f, l = 0.f;
    float ctx[PH];
    #pragma unroll
    for (int d = 0; d < PH; ++d) ctx[d] = 0.f;

    for (int ti = 0; ti < 8; ++ti) {
        asm volatile("cp.async.wait_group 0;");
        __syncthreads();
        if (ti + 1 < 8) load_tile((ti + 1) & 1, ti + 1);

        const float* kbase = kv_s + (ti & 1) * 4352;
        #pragma unroll
        for (int cc = 0; cc < 2; ++cc) {
            const int key = ti * 64 + cc * 32 + lane;
            const float4* kp = (const float4*)(kbase + (cc * 32 + lane) * 68);
            float s0 = 0.f, s1 = 0.f, s2 = 0.f, s3 = 0.f;
            #pragma unroll
            for (int j = 0; j < 8; ++j) {
                float4 kvv = kp[j];
                s0 = fmaf(qv[j * 4 + 0], kvv.x, s0);
                s1 = fmaf(qv[j * 4 + 1], kvv.y, s1);
                s2 = fmaf(qv[j * 4 + 2], kvv.z, s2);
                s3 = fmaf(qv[j * 4 + 3], kvv.w, s3);
            }
            int rmv = rmrow[key];
            float s = (s0 + s1) + (s2 + s3) + qrel_s[w * 100 + rmv];

            float cmax = s;
            #pragma unroll
            for (int off = 16; off > 0; off >>= 1)
                cmax = fmaxf(cmax, __shfl_xor_sync(0xffffffffu, cmax, off));
            if (cmax > m) {                      // warp-uniform branch
                float alpha = __expf(m - cmax);
                l *= alpha;
                #pragma unroll
                for (int d = 0; d < PH; ++d) ctx[d] *= alpha;
                // FIX: histogram holds exp(s - m_old) terms; rescale them.
                for (int r = lane; r < NREL; r += 32)
                    mass_s[w * 100 + r] *= alpha;
                m = cmax;
                __syncwarp();   // rescale done before any lane's atomicAdd
            }
            float p = __expf(s - m);
            l += p;
            atomicAdd(&mass_s[w * 100 + rmv], p);
            const float4* vp = (const float4*)(kbase + (cc * 32 + lane) * 68 + 36);
            #pragma unroll
            for (int j = 0; j < 8; ++j) {
                float4 vv = vp[j];
                ctx[j * 4 + 0] = fmaf(p, vv.x, ctx[j * 4 + 0]);
                ctx[j * 4 + 1] = fmaf(p, vv.y, ctx[j * 4 + 1]);
                ctx[j * 4 + 2] = fmaf(p, vv.z, ctx[j * 4 + 2]);
                ctx[j * 4 + 3] = fmaf(p, vv.w, ctx[j * 4 + 3]);
            }
        }
    }

    #pragma unroll
    for (int off = 16; off > 0; off >>= 1) {
        l += __shfl_xor_sync(0xffffffffu, l, off);
        #pragma unroll
        for (int d = 0; d < PH; ++d)
            ctx[d] += __shfl_xor_sync(0xffffffffu, ctx[d], off);
    }
    __syncwarp();

    if (lane == 0) {
        #pragma unroll
        for (int d = 0; d < PH; ++d) tmp_s[w * 32 + d] = ctx[d];
    }
    __syncwarp();

    // lane d finalizes dim d: (ctx[d] + sum_r mass[r]*rel_v[r][d]) / l
    float cd = tmp_s[w * 32 + lane];
    float racc = 0.f;
    #pragma unroll 4
    for (int r = 0; r < NREL; ++r)
        racc = fmaf(mass_s[w * 100 + r], relv_s[r * 33 + lane], racc);

    float val = (cd + racc) / l;
    __nv_bfloat16 hv = __float2bfloat16(val);
    size_t oidx = (size_t)(b * SEQ + q) * DH + h * PH + lane;
    ctxh[oidx] = hv;
    ctxl[oidx] = __float2bfloat16(val - __bfloat162float(hv));
}

// ----------------------------- launch -----------------------------------
extern "C" void kernel_launch(void* const* d_in, const int* in_sizes, int n_in,
                              void* d_out, int out_size)
{
    const float* hidden = (const float*)d_in[0];
    const float* Wq = (const float*)d_in[1];
    const float* bq = (const float*)d_in[2];
    const float* Wk = (const float*)d_in[3];
    const float* bk = (const float*)d_in[4];
    const float* Wv = (const float*)d_in[5];
    const float* bv = (const float*)d_in[6];
    const float* Wo = (const float*)d_in[7];
    const float* bo = (const float*)d_in[8];
    const float* rke = (const float*)d_in[9];
    const float* rve = (const float*)d_in[10];
    const float* W1 = (const float*)d_in[11];
    const float* b1 = (const float*)d_in[12];
    const float* W2 = (const float*)d_in[13];
    const float* b2 = (const float*)d_in[14];
    const int*   rm = (const int*)d_in[15];
    float* out = (float*)d_out;

    float *Qb, *Kb, *Vb;
    cudaGetSymbolAddress((void**)&Qb, g_Q);
    cudaGetSymbolAddress((void**)&Kb, g_K);
    cudaGetSymbolAddress((void**)&Vb, g_V);
    __nv_bfloat16 *hh, *hl, *ch, *cl, *ah, *al, *h1h, *h1l, *Wh, *Wl;
    cudaGetSymbolAddress((void**)&hh, g_hh);
    cudaGetSymbolAddress((void**)&hl, g_hl);
    cudaGetSymbolAddress((void**)&ch, g_ch);
    cudaGetSymbolAddress((void**)&cl, g_cl);
    cudaGetSymbolAddress((void**)&ah, g_ah);
    cudaGetSymbolAddress((void**)&al, g_al);
    cudaGetSymbolAddress((void**)&h1h, g_1h);
    cudaGetSymbolAddress((void**)&h1l, g_1l);
    cudaGetSymbolAddress((void**)&Wh, g_Wh);
    cudaGetSymbolAddress((void**)&Wl, g_Wl);

    cudaFuncSetAttribute(attn_v4,
        cudaFuncAttributeMaxDynamicSharedMemorySize, ATTN_SMEM);
    cudaFuncSetAttribute(hgemm_v4,
        cudaFuncAttributeMaxDynamicSharedMemorySize, GSMEM);

    // 1) all 6 weights in ONE launch
    dim3 cb(32, 8), cg(DH / 32, DH / 32, 6);
    convert_weight6<<<cg, cb>>>(Wq, Wk, Wv, Wo, W1, W2, Wh, Wl);

    // 2) split hidden
    split_act<<<(TOKS * DH) / (256 * 4), 256>>>(hidden, hh, hl);

    size_t WW = (size_t)DH * DH;
    dim3 gg(DH / 80, TOKS / 128);   // (20, 16)

    // 3-5) Q, K, V projections (fp32 out for attention)
    hgemm_v4<<<gg, 256, GSMEM>>>(hh, hl, Wh + 0 * WW, Wl + 0 * WW, bq,
                                 Qb, nullptr, nullptr, 0, 0);
    hgemm_v4<<<gg, 256, GSMEM>>>(hh, hl, Wh + 1 * WW, Wl + 1 * WW, bk,
                                 Kb, nullptr, nullptr, 0, 0);
    hgemm_v4<<<gg, 256, GSMEM>>>(hh, hl, Wh + 2 * WW, Wl + 2 * WW, bv,
                                 Vb, nullptr, nullptr, 0, 0);

    // 6) attention -> ctx split
    dim3 ag(BATCH * NHEADS, SEQ / 16);  // (200, 32)
    attn_v4<<<ag, 512, ATTN_SMEM>>>(Qb, Kb, Vb, rke, rve, rm, ch, cl);

    // 7) Wo -> attn_out split
    hgemm_v4<<<gg, 256, GSMEM>>>(ch, cl, Wh + 3 * WW, Wl + 3 * WW, bo,
                                 nullptr, ah, al, 0, 1);
    // 8) W1 + gelu -> h1 split
    hgemm_v4<<<gg, 256, GSMEM>>>(ah, al, Wh + 4 * WW, Wl + 4 * WW, b1,
                                 nullptr, h1h, h1l, 1, 1);
    // 9) W2 -> final fp32 out
    hgemm_v4<<<gg, 256, GSMEM>>>(h1h, h1l, Wh + 5 * WW, Wl + 5 * WW, b2,
                                 out, nullptr, nullptr, 0, 0);
}

// round 12
// speedup vs baseline: 1.7358x; 1.0019x over previous
#include <cuda_runtime.h>
#include <cuda_bf16.h>
#include <math.h>
#include <stdint.h>

#define BATCH 4
#define SEQ   512
#define TOKS  (BATCH*SEQ)      // 2048
#define DH    1600
#define NHEADS 50
#define PH    32
#define NREL  100

// ---------------- static scratch (no allocation allowed) ----------------
__device__ float g_Q[TOKS*DH];
__device__ float g_K[TOKS*DH];
__device__ float g_V[TOKS*DH];
__device__ __nv_bfloat16 g_hh[TOKS*DH], g_hl[TOKS*DH];   // hidden split
__device__ __nv_bfloat16 g_ch[TOKS*DH], g_cl[TOKS*DH];   // ctx split
__device__ __nv_bfloat16 g_ah[TOKS*DH], g_al[TOKS*DH];   // attn_out split
__device__ __nv_bfloat16 g_1h[TOKS*DH], g_1l[TOKS*DH];   // h1 split
__device__ __nv_bfloat16 g_Wh[6][DH*DH];
__device__ __nv_bfloat16 g_Wl[6][DH*DH];

// ------------- batched weight convert: W[K][N] fp32 -> [N][K] bf16 hi/lo
__global__ __launch_bounds__(256) void convert_weight6(
    const float* W0, const float* W1, const float* W2,
    const float* W3, const float* W4, const float* W5,
    __nv_bfloat16* __restrict__ hi_base, __nv_bfloat16* __restrict__ lo_base)
{
    __shared__ float t[32][33];
    const int wi = blockIdx.z;
    const float* W = (wi == 0) ? W0 : (wi == 1) ? W1 : (wi == 2) ? W2 :
                     (wi == 3) ? W3 : (wi == 4) ? W4 : W5;
    __nv_bfloat16* hi = hi_base + (size_t)wi * DH * DH;
    __nv_bfloat16* lo = lo_base + (size_t)wi * DH * DH;
    const int n0 = blockIdx.x * 32, k0 = blockIdx.y * 32;
    const int tx = threadIdx.x, ty = threadIdx.y;   // (32,8)
    #pragma unroll
    for (int j = 0; j < 32; j += 8)
        t[ty + j][tx] = W[(size_t)(k0 + ty + j) * DH + n0 + tx];
    __syncthreads();
    #pragma unroll
    for (int j = 0; j < 32; j += 8) {
        float v = t[tx][ty + j];
        __nv_bfloat16 h = __float2bfloat16(v);
        __nv_bfloat16 l = __float2bfloat16(v - __bfloat162float(h));
        size_t o = (size_t)(n0 + ty + j) * DH + k0 + tx;
        hi[o] = h; lo[o] = l;
    }
}

// ------------- activation split: fp32 -> bf16 hi/lo ---------------------
__global__ __launch_bounds__(256) void split_act(
    const float* __restrict__ x,
    __nv_bfloat16* __restrict__ hi, __nv_bfloat16* __restrict__ lo)
{
    size_t i = ((size_t)blockIdx.x * 256 + threadIdx.x) * 4;
    float4 v = *(const float4*)(x + i);
    __nv_bfloat16 hx = __float2bfloat16(v.x), hy = __float2bfloat16(v.y);
    __nv_bfloat16 hz = __float2bfloat16(v.z), hw = __float2bfloat16(v.w);
    __nv_bfloat162 h01; h01.x = hx; h01.y = hy;
    __nv_bfloat162 h23; h23.x = hz; h23.y = hw;
    *(__nv_bfloat162*)(hi + i)     = h01;
    *(__nv_bfloat162*)(hi + i + 2) = h23;
    __nv_bfloat162 l01, l23;
    l01.x = __float2bfloat16(v.x - __bfloat162float(hx));
    l01.y = __float2bfloat16(v.y - __bfloat162float(hy));
    l23.x = __float2bfloat16(v.z - __bfloat162float(hz));
    l23.y = __float2bfloat16(v.w - __bfloat162float(hw));
    *(__nv_bfloat162*)(lo + i)     = l01;
    *(__nv_bfloat162*)(lo + i + 2) = l23;
}

// ------------- bf16x3 tensor-core GEMM, ldmatrix + 2-stage cp.async -----
// BM=128 BN=80 BK=32, 256 thr = 8 warps (4m x 2n), warp tile 32x40.
// stage words: Ahi 2560 | Alo 2560 | Bhi 1600 | Blo 1600 = 8320
#define GSTAGE 8320
#define GSMEM  (2 * GSTAGE * 4)

__device__ __forceinline__ void mma16816(float* c, const uint32_t* a,
                                         uint32_t b0, uint32_t b1) {
    asm volatile(
        "mma.sync.aligned.m16n8k16.row.col.f32.bf16.bf16.f32 "
        "{%0,%1,%2,%3}, {%4,%5,%6,%7}, {%8,%9}, {%0,%1,%2,%3};"
        : "+f"(c[0]), "+f"(c[1]), "+f"(c[2]), "+f"(c[3])
        : "r"(a[0]), "r"(a[1]), "r"(a[2]), "r"(a[3]), "r"(b0), "r"(b1));
}
__device__ __forceinline__ void cpasync16(uint32_t dst, const void* src) {
    asm volatile("cp.async.cg.shared.global [%0], [%1], 16;"
                 :: "r"(dst), "l"(src));
}
__device__ __forceinline__ void ldsm4(uint32_t* r, uint32_t a) {
    asm volatile("ldmatrix.sync.aligned.m8n8.x4.shared.b16 {%0,%1,%2,%3}, [%4];"
                 : "=r"(r[0]), "=r"(r[1]), "=r"(r[2]), "=r"(r[3]) : "r"(a));
}

__global__ __launch_bounds__(256, 2) void hgemm_v4(
    const __nv_bfloat16* __restrict__ Ah, const __nv_bfloat16* __restrict__ Al,
    const __nv_bfloat16* __restrict__ Bh, const __nv_bfloat16* __restrict__ Bl,
    const float* __restrict__ bias,
    float* __restrict__ Cf,
    __nv_bfloat16* __restrict__ Ch, __nv_bfloat16* __restrict__ Cl,
    int act, int mode)   // mode 0: fp32 out; mode 1: split bf16 out
{
    extern __shared__ uint32_t smw[];
    const uint32_t sm0 = (uint32_t)__cvta_generic_to_shared(smw);

    const int tid  = threadIdx.x;
    const int lane = tid & 31, warp = tid >> 5;
    const int wm = warp >> 1, wn = warp & 1;
    const int g = lane >> 2, t4 = lane & 3;
    const int bm = blockIdx.y * 128, bn = blockIdx.x * 80;

    float acc[2][5][4];
    #pragma unroll
    for (int mt = 0; mt < 2; ++mt)
        #pragma unroll
        for (int nt = 0; nt < 5; ++nt)
            #pragma unroll
            for (int i = 0; i < 4; ++i) acc[mt][nt][i] = 0.f;

    // ldmatrix per-lane byte offsets within a stage
    const uint32_t aRow = wm * 32 + (lane & 7) + 8 * ((lane >> 3) & 1);
    const uint32_t aOff = (aRow * 20 + 4 * (lane >> 4)) * 4;
    const uint32_t bOff = (5120 + (wn * 40 + (lane & 7)) * 20 + 4 * (lane >> 3)) * 4;

    auto load_tile = [&](int stage, int kk) {
        uint32_t sb = sm0 + stage * GSTAGE * 4;
        #pragma unroll
        for (int it = 0; it < 4; ++it) {         // A: 1024 16B chunks
            int idx = tid + it * 256;
            int hl = idx >> 9;
            int r  = (idx >> 2) & 127;
            int c  = idx & 3;
            const __nv_bfloat16* src =
                (hl ? Al : Ah) + (size_t)(bm + r) * DH + kk + c * 8;
            cpasync16(sb + (hl * 2560 + r * 20 + c * 4) * 4, src);
        }
        for (int idx = tid; idx < 640; idx += 256) {  // B: 640 chunks
            int hl = idx >= 320;
            int j  = idx - hl * 320;
            int r  = j >> 2, c = j & 3;
            const __nv_bfloat16* src =
                (hl ? Bl : Bh) + (size_t)(bn + r) * DH + kk + c * 8;
            cpasync16(sb + (5120 + hl * 1600 + r * 20 + c * 4) * 4, src);
        }
        asm volatile("cp.async.commit_group;");
    };

    const int NT = DH / 32;   // 50
    load_tile(0, 0);

    for (int t = 0; t < NT; ++t) {
        int cur = t & 1;
        if (t + 1 < NT) {
            load_tile(cur ^ 1, (t + 1) * 32);
            asm volatile("cp.async.wait_group 1;");
        } else {
            asm volatile("cp.async.wait_group 0;");
        }
        __syncthreads();

        const uint32_t sb = sm0 + cur * GSTAGE * 4;

        uint32_t bh[5][4], bl[5][4];
        #pragma unroll
        for (int nt = 0; nt < 5; ++nt) {
            ldsm4(bh[nt], sb + bOff + nt * (8 * 20 * 4));
            ldsm4(bl[nt], sb + bOff + nt * (8 * 20 * 4) + 1600 * 4);
        }

        #pragma unroll
        for (int kh = 0; kh < 2; ++kh) {          // two k16 halves
            const int ks = kh * 8, o = kh * 2;
            uint32_t ah[2][4], al[2][4];
            #pragma unroll
            for (int mt = 0; mt < 2; ++mt) {
                uint32_t a = sb + aOff + (mt * 16 * 20 + ks) * 4;
                ldsm4(ah[mt], a);
                ldsm4(al[mt], a + 2560 * 4);
            }
            #pragma unroll
            for (int nt = 0; nt < 5; ++nt) {
                #pragma unroll
                for (int mt = 0; mt < 2; ++mt) {
                    mma16816(acc[mt][nt], ah[mt], bh[nt][o], bh[nt][o + 1]);
                    mma16816(acc[mt][nt], ah[mt], bl[nt][o], bl[nt][o + 1]);
                    mma16816(acc[mt][nt], al[mt], bh[nt][o], bh[nt][o + 1]);
                }
            }
        }
        __syncthreads();
    }

    // ---- epilogue ----
    #pragma unroll
    for (int mt = 0; mt < 2; ++mt) {
        #pragma unroll
        for (int nt = 0; nt < 5; ++nt) {
            int r0 = bm + wm * 32 + mt * 16 + g;
            int c0 = bn + wn * 40 + nt * 8 + t4 * 2;
            float b0v = bias[c0], b1v = bias[c0 + 1];
            float x0 = acc[mt][nt][0] + b0v, x1 = acc[mt][nt][1] + b1v;
            float x2 = acc[mt][nt][2] + b0v, x3 = acc[mt][nt][3] + b1v;
            if (act) {
                x0 = 0.5f * x0 * (1.f + erff(x0 * 0.70710678118654752f));
                x1 = 0.5f * x1 * (1.f + erff(x1 * 0.70710678118654752f));
                x2 = 0.5f * x2 * (1.f + erff(x2 * 0.70710678118654752f));
                x3 = 0.5f * x3 * (1.f + erff(x3 * 0.70710678118654752f));
            }
            if (mode == 0) {
                *(float2*)(Cf + (size_t)r0 * DH + c0)       = make_float2(x0, x1);
                *(float2*)(Cf + (size_t)(r0 + 8) * DH + c0) = make_float2(x2, x3);
            } else {
                __nv_bfloat162 h01, h23, l01, l23;
                h01.x = __float2bfloat16(x0); h01.y = __float2bfloat16(x1);
                h23.x = __float2bfloat16(x2); h23.y = __float2bfloat16(x3);
                l01.x = __float2bfloat16(x0 - __bfloat162float(h01.x));
                l01.y = __float2bfloat16(x1 - __bfloat162float(h01.y));
                l23.x = __float2bfloat16(x2 - __bfloat162float(h23.x));
                l23.y = __float2bfloat16(x3 - __bfloat162float(h23.y));
                *(__nv_bfloat162*)(Ch + (size_t)r0 * DH + c0)       = h01;
                *(__nv_bfloat162*)(Ch + (size_t)(r0 + 8) * DH + c0) = h23;
                *(__nv_bfloat162*)(Cl + (size_t)r0 * DH + c0)       = l01;
                *(__nv_bfloat162*)(Cl + (size_t)(r0 + 8) * DH + c0) = l23;
            }
        }
    }
}

// ------------- attention v4b: single-pass online softmax ----------------
// FIX vs R9: on max update, rescale the per-warp relation-mass histogram
// by alpha too (it holds exp(s - m) terms; m changed). Warp-uniform branch,
// lanes cover distinct bins, __syncwarp before subsequent atomicAdds.
#define ATTN_SMEM (19016 * 4)

__global__ __launch_bounds__(512) void attn_v4(
    const float* __restrict__ Q, const float* __restrict__ Kg,
    const float* __restrict__ Vg,
    const float* __restrict__ relk, const float* __restrict__ relv,
    const int* __restrict__ rm,
    __nv_bfloat16* __restrict__ ctxh, __nv_bfloat16* __restrict__ ctxl)
{
    extern __shared__ float sm[];
    float* relk_s = sm;                 // [100][33]
    float* relv_s = sm + 3300;          // [100][33]
    float* kv_s   = sm + 6600;          // [2][64][68]
    float* qrel_s = sm + 15304;         // [16][100]
    float* mass_s = sm + 16904;         // [16][100]
    float* tmp_s  = sm + 18504;         // [16][32]
    const uint32_t kv0 = (uint32_t)__cvta_generic_to_shared(kv_s);

    const int tid  = threadIdx.x;
    const int w    = tid >> 5, lane = tid & 31;
    const int b    = blockIdx.x / NHEADS, h = blockIdx.x % NHEADS;
    const int q    = blockIdx.y * 16 + w;
    const float scale = 0.1767766952966369f;  // 1/sqrt(32)

    for (int i = tid; i < NREL * PH; i += 512) {
        int r = i >> 5, d = i & 31;
        relk_s[r * 33 + d] = relk[i];
        relv_s[r * 33 + d] = relv[i];
    }
    tmp_s[tid] = Q[(size_t)(b * SEQ + q) * DH + h * PH + lane];
    __syncthreads();

    float qv[PH];
    #pragma unroll
    for (int d = 0; d < PH; ++d) qv[d] = tmp_s[w * 32 + d] * scale;

    for (int r = lane; r < NREL; r += 32) {
        float a0 = 0.f, a1 = 0.f, a2 = 0.f, a3 = 0.f;
        #pragma unroll
        for (int d = 0; d < PH; d += 4) {
            a0 = fmaf(qv[d + 0], relk_s[r * 33 + d + 0], a0);
            a1 = fmaf(qv[d + 1], relk_s[r * 33 + d + 1], a1);
            a2 = fmaf(qv[d + 2], relk_s[r * 33 + d + 2], a2);
            a3 = fmaf(qv[d + 3], relk_s[r * 33 + d + 3], a3);
        }
        qrel_s[w * 100 + r] = (a0 + a1) + (a2 + a3);
        mass_s[w * 100 + r] = 0.f;
    }
    __syncwarp();

    const int* rmrow = rm + ((size_t)(b * SEQ + q)) * SEQ;

    auto load_tile = [&](int stage, int ti) {
        #pragma unroll
        for (int it = 0; it < 2; ++it) {
            int idx = tid + it * 512;
            int half = idx >> 9;                 // 0 = K, 1 = V
            int j = idx & 511;
            int r = j >> 3, c4 = j & 7;
            const float* src = (half ? Vg : Kg) +
                (size_t)(b * SEQ + ti * 64 + r) * DH + h * PH + c4 * 4;
            cpasync16(kv0 + (stage * 4352 + r * 68 + half * 36 + c4 * 4) * 4, src);
        }
        asm volatile("cp.async.commit_group;");
    };

    load_tile(0, 0);

    float m = -1e30f, l = 0.f;
    float ctx[PH];
    #pragma unroll
    for (int d = 0; d < PH; ++d) ctx[d] = 0.f;

    for (int ti = 0; ti < 8; ++ti) {
        asm volatile("cp.async.wait_group 0;");
        __syncthreads();
        if (ti + 1 < 8) load_tile((ti + 1) & 1, ti + 1);

        const float* kbase = kv_s + (ti & 1) * 4352;
        #pragma unroll
        for (int cc = 0; cc < 2; ++cc) {
            const int key = ti * 64 + cc * 32 + lane;
            const float4* kp = (const float4*)(kbase + (cc * 32 + lane) * 68);
            float s0 = 0.f, s1 = 0.f, s2 = 0.f, s3 = 0.f;
            #pragma unroll
            for (int j = 0; j < 8; ++j) {
                float4 kvv = kp[j];
                s0 = fmaf(qv[j * 4 + 0], kvv.x, s0);
                s1 = fmaf(qv[j * 4 + 1], kvv.y, s1);
                s2 = fmaf(qv[j * 4 + 2], kvv.z, s2);
                s3 = fmaf(qv[j * 4 + 3], kvv.w, s3);
            }
            int rmv = rmrow[key];
            float s = (s0 + s1) + (s2 + s3) + qrel_s[w * 100 + rmv];

            float cmax = s;
            #pragma unroll
            for (int off = 16; off > 0; off >>= 1)
                cmax = fmaxf(cmax, __shfl_xor_sync(0xffffffffu, cmax, off));
            if (cmax > m) {                      // warp-uniform branch
                float alpha = __expf(m - cmax);
                l *= alpha;
                #pragma unroll
                for (int d = 0; d < PH; ++d) ctx[d] *= alpha;
                // FIX: histogram holds exp(s - m_old) terms; rescale them.
                for (int r = lane; r < NREL; r += 32)
                    mass_s[w * 100 + r] *= alpha;
                m = cmax;
                __syncwarp();   // rescale done before any lane's atomicAdd
            }
            float p = __expf(s - m);
            l += p;
            atomicAdd(&mass_s[w * 100 + rmv], p);
            const float4* vp = (const float4*)(kbase + (cc * 32 + lane) * 68 + 36);
            #pragma unroll
            for (int j = 0; j < 8; ++j) {
                float4 vv = vp[j];
                ctx[j * 4 + 0] = fmaf(p, vv.x, ctx[j * 4 + 0]);
                ctx[j * 4 + 1] = fmaf(p, vv.y, ctx[j * 4 + 1]);
                ctx[j * 4 + 2] = fmaf(p, vv.z, ctx[j * 4 + 2]);
                ctx[j * 4 + 3] = fmaf(p, vv.w, ctx[j * 4 + 3]);
            }
        }
    }

    #pragma unroll
    for (int off = 16; off > 0; off >>= 1) {
        l += __shfl_xor_sync(0xffffffffu, l, off);
        #pragma unroll
        for (int d = 0; d < PH; ++d)
            ctx[d] += __shfl_xor_sync(0xffffffffu, ctx[d], off);
    }
    __syncwarp();

    if (lane == 0) {
        #pragma unroll
        for (int d = 0; d < PH; ++d) tmp_s[w * 32 + d] = ctx[d];
    }
    __syncwarp();

    // lane d finalizes dim d: (ctx[d] + sum_r mass[r]*rel_v[r][d]) / l
    float cd = tmp_s[w * 32 + lane];
    float racc = 0.f;
    #pragma unroll 4
    for (int r = 0; r < NREL; ++r)
        racc = fmaf(mass_s[w * 100 + r], relv_s[r * 33 + lane], racc);

    float val = (cd + racc) / l;
    __nv_bfloat16 hv = __float2bfloat16(val);
    size_t oidx = (size_t)(b * SEQ + q) * DH + h * PH + lane;
    ctxh[oidx] = hv;
    ctxl[oidx] = __float2bfloat16(val - __bfloat162float(hv));
}

// ----------------------------- launch -----------------------------------
extern "C" void kernel_launch(void* const* d_in, const int* in_sizes, int n_in,
                              void* d_out, int out_size)
{
    const float* hidden = (const float*)d_in[0];
    const float* Wq = (const float*)d_in[1];
    const float* bq = (const float*)d_in[2];
    const float* Wk = (const float*)d_in[3];
    const float* bk = (const float*)d_in[4];
    const float* Wv = (const float*)d_in[5];
    const float* bv = (const float*)d_in[6];
    const float* Wo = (const float*)d_in[7];
    const float* bo = (const float*)d_in[8];
    const float* rke = (const float*)d_in[9];
    const float* rve = (const float*)d_in[10];
    const float* W1 = (const float*)d_in[11];
    const float* b1 = (const float*)d_in[12];
    const float* W2 = (const float*)d_in[13];
    const float* b2 = (const float*)d_in[14];
    const int*   rm = (const int*)d_in[15];
    float* out = (float*)d_out;

    float *Qb, *Kb, *Vb;
    cudaGetSymbolAddress((void**)&Qb, g_Q);
    cudaGetSymbolAddress((void**)&Kb, g_K);
    cudaGetSymbolAddress((void**)&Vb, g_V);
    __nv_bfloat16 *hh, *hl, *ch, *cl, *ah, *al, *h1h, *h1l, *Wh, *Wl;
    cudaGetSymbolAddress((void**)&hh, g_hh);
    cudaGetSymbolAddress((void**)&hl, g_hl);
    cudaGetSymbolAddress((void**)&ch, g_ch);
    cudaGetSymbolAddress((void**)&cl, g_cl);
    cudaGetSymbolAddress((void**)&ah, g_ah);
    cudaGetSymbolAddress((void**)&al, g_al);
    cudaGetSymbolAddress((void**)&h1h, g_1h);
    cudaGetSymbolAddress((void**)&h1l, g_1l);
    cudaGetSymbolAddress((void**)&Wh, g_Wh);
    cudaGetSymbolAddress((void**)&Wl, g_Wl);

    cudaFuncSetAttribute(attn_v4,
        cudaFuncAttributeMaxDynamicSharedMemorySize, ATTN_SMEM);
    cudaFuncSetAttribute(hgemm_v4,
        cudaFuncAttributeMaxDynamicSharedMemorySize, GSMEM);

    // 1) all 6 weights in ONE launch
    dim3 cb(32, 8), cg(DH / 32, DH / 32, 6);
    convert_weight6<<<cg, cb>>>(Wq, Wk, Wv, Wo, W1, W2, Wh, Wl);

    // 2) split hidden
    split_act<<<(TOKS * DH) / (256 * 4), 256>>>(hidden, hh, hl);

    size_t WW = (size_t)DH * DH;
    dim3 gg(DH / 80, TOKS / 128);   // (20, 16)

    // 3-5) Q, K, V projections (fp32 out for attention)
    hgemm_v4<<<gg, 256, GSMEM>>>(hh, hl, Wh + 0 * WW, Wl + 0 * WW, bq,
                                 Qb, nullptr, nullptr, 0, 0);
    hgemm_v4<<<gg, 256, GSMEM>>>(hh, hl, Wh + 1 * WW, Wl + 1 * WW, bk,
                                 Kb, nullptr, nullptr, 0, 0);
    hgemm_v4<<<gg, 256, GSMEM>>>(hh, hl, Wh + 2 * WW, Wl + 2 * WW, bv,
                                 Vb, nullptr, nullptr, 0, 0);

    // 6) attention -> ctx split
    dim3 ag(BATCH * NHEADS, SEQ / 16);  // (200, 32)
    attn_v4<<<ag, 512, ATTN_SMEM>>>(Qb, Kb, Vb, rke, rve, rm, ch, cl);

    // 7) Wo -> attn_out split
    hgemm_v4<<<gg, 256, GSMEM>>>(ch, cl, Wh + 3 * WW, Wl + 3 * WW, bo,
                                 nullptr, ah, al, 0, 1);
    // 8) W1 + gelu -> h1 split
    hgemm_v4<<<gg, 256, GSMEM>>>(ah, al, Wh + 4 * WW, Wl + 4 * WW, b1,
                                 nullptr, h1h, h1l, 1, 1);
    // 9) W2 -> final fp32 out
    hgemm_v4<<<gg, 256, GSMEM>>>(h1h, h1l, Wh + 5 * WW, Wl + 5 * WW, b2,
                                 out, nullptr, nullptr, 0, 0);
}

// round 13
// speedup vs baseline: 2.3698x; 1.3652x over previous
#include <cuda_runtime.h>
#include <cuda_bf16.h>
#include <math.h>
#include <stdint.h>

#define BATCH 4
#define SEQ   512
#define TOKS  (BATCH*SEQ)
#define DH    1600
#define NHEADS 50
#define PH    32
#define NREL  100

__device__ __nv_bfloat16 g_hh[TOKS*DH], g_hl[TOKS*DH];
__device__ __nv_bfloat16 g_qh[TOKS*DH], g_ql[TOKS*DH];
__device__ __nv_bfloat16 g_kh[TOKS*DH], g_kl[TOKS*DH];
__device__ __nv_bfloat16 g_vh[TOKS*DH], g_vl[TOKS*DH];
__device__ __nv_bfloat16 g_ch[TOKS*DH], g_cl[TOKS*DH];
__device__ __nv_bfloat16 g_ah[TOKS*DH], g_al[TOKS*DH];
__device__ __nv_bfloat16 g_1h[TOKS*DH], g_1l[TOKS*DH];
__device__ __nv_bfloat16 g_Wh[6][DH*DH];
__device__ __nv_bfloat16 g_Wl[6][DH*DH];

__global__ __launch_bounds__(256) void convert_weight6(
    const float* W0, const float* W1, const float* W2,
    const float* W3, const float* W4, const float* W5,
    __nv_bfloat16* __restrict__ hi_base, __nv_bfloat16* __restrict__ lo_base)
{
    __shared__ float t[32][33];
    const int wi = blockIdx.z;
    const float* W = (wi == 0) ? W0 : (wi == 1) ? W1 : (wi == 2) ? W2 :
                     (wi == 3) ? W3 : (wi == 4) ? W4 : W5;
    __nv_bfloat16* hi = hi_base + (size_t)wi * DH * DH;
    __nv_bfloat16* lo = lo_base + (size_t)wi * DH * DH;
    const int n0 = blockIdx.x * 32, k0 = blockIdx.y * 32;
    const int tx = threadIdx.x, ty = threadIdx.y;
    #pragma unroll
    for (int j = 0; j < 32; j += 8)
        t[ty + j][tx] = W[(size_t)(k0 + ty + j) * DH + n0 + tx];
    __syncthreads();
    #pragma unroll
    for (int j = 0; j < 32; j += 8) {
        float v = t[tx][ty + j];
        __nv_bfloat16 h = __float2bfloat16(v);
        __nv_bfloat16 l = __float2bfloat16(v - __bfloat162float(h));
        size_t o = (size_t)(n0 + ty + j) * DH + k0 + tx;
        hi[o] = h; lo[o] = l;
    }
}

__global__ __launch_bounds__(256) void split_act(
    const float* __restrict__ x,
    __nv_bfloat16* __restrict__ hi, __nv_bfloat16* __restrict__ lo)
{
    size_t i = ((size_t)blockIdx.x * 256 + threadIdx.x) * 4;
    float4 v = *(const float4*)(x + i);
    __nv_bfloat16 hx = __float2bfloat16(v.x), hy = __float2bfloat16(v.y);
    __nv_bfloat16 hz = __float2bfloat16(v.z), hw = __float2bfloat16(v.w);
    __nv_bfloat162 h01; h01.x = hx; h01.y = hy;
    __nv_bfloat162 h23; h23.x = hz; h23.y = hw;
    *(__nv_bfloat162*)(hi + i)     = h01;
    *(__nv_bfloat162*)(hi + i + 2) = h23;
    __nv_bfloat162 l01, l23;
    l01.x = __float2bfloat16(v.x - __bfloat162float(hx));
    l01.y = __float2bfloat16(v.y - __bfloat162float(hy));
    l23.x = __float2bfloat16(v.z - __bfloat162float(hz));
    l23.y = __float2bfloat16(v.w - __bfloat162float(hw));
    *(__nv_bfloat162*)(lo + i)     = l01;
    *(__nv_bfloat162*)(lo + i + 2) = l23;
}

#define GSTAGE 8320
#define GSMEM  (2 * GSTAGE * 4)

__device__ __forceinline__ void mma16816(float* c, const uint32_t* a,
                                         uint32_t b0, uint32_t b1) {
    asm volatile(
        "mma.sync.aligned.m16n8k16.row.col.f32.bf16.bf16.f32 "
        "{%0,%1,%2,%3}, {%4,%5,%6,%7}, {%8,%9}, {%0,%1,%2,%3};"
        : "+f"(c[0]), "+f"(c[1]), "+f"(c[2]), "+f"(c[3])
        : "r"(a[0]), "r"(a[1]), "r"(a[2]), "r"(a[3]), "r"(b0), "r"(b1));
}
__device__ __forceinline__ void cpasync16(uint32_t dst, const void* src) {
    asm volatile("cp.async.cg.shared.global [%0], [%1], 16;"
                 :: "r"(dst), "l"(src));
}
__device__ __forceinline__ void ldsm4(uint32_t* r, uint32_t a) {
    asm volatile("ldmatrix.sync.aligned.m8n8.x4.shared.b16 {%0,%1,%2,%3}, [%4];"
                 : "=r"(r[0]), "=r"(r[1]), "=r"(r[2]), "=r"(r[3]) : "r"(a));
}
__device__ __forceinline__ void ldsm2t(uint32_t* r, uint32_t a) {
    asm volatile("ldmatrix.sync.aligned.m8n8.x2.trans.shared.b16 {%0,%1}, [%2];"
                 : "=r"(r[0]), "=r"(r[1]) : "r"(a));
}
__device__ __forceinline__ uint32_t packbf(__nv_bfloat16 a, __nv_bfloat16 b) {
    return (uint32_t)__bfloat16_as_ushort(a) |
           ((uint32_t)__bfloat16_as_ushort(b) << 16);
}

__global__ __launch_bounds__(256, 2) void hgemm_v4(
    const __nv_bfloat16* __restrict__ Ah, const __nv_bfloat16* __restrict__ Al,
    const __nv_bfloat16* __restrict__ Bh, const __nv_bfloat16* __restrict__ Bl,
    const float* __restrict__ bias,
    float* __restrict__ Cf,
    __nv_bfloat16* __restrict__ Ch, __nv_bfloat16* __restrict__ Cl,
    int act, int mode)
{
    extern __shared__ uint32_t smw[];
    const uint32_t sm0 = (uint32_t)__cvta_generic_to_shared(smw);
    const int tid  = threadIdx.x;
    const int lane = tid & 31, warp = tid >> 5;
    const int wm = warp >> 1, wn = warp & 1;
    const int g = lane >> 2, t4 = lane & 3;
    const int bm = blockIdx.y * 128, bn = blockIdx.x * 80;

    float acc[2][5][4];
    #pragma unroll
    for (int mt = 0; mt < 2; ++mt)
        #pragma unroll
        for (int nt = 0; nt < 5; ++nt)
            #pragma unroll
            for (int i = 0; i < 4; ++i) acc[mt][nt][i] = 0.f;

    const uint32_t aRow = wm * 32 + (lane & 7) + 8 * ((lane >> 3) & 1);
    const uint32_t aOff = (aRow * 20 + 4 * (lane >> 4)) * 4;
    const uint32_t bOff = (5120 + (wn * 40 + (lane & 7)) * 20 + 4 * (lane >> 3)) * 4;

    auto load_tile = [&](int stage, int kk) {
        uint32_t sb = sm0 + stage * GSTAGE * 4;
        #pragma unroll
        for (int it = 0; it < 4; ++it) {
            int idx = tid + it * 256;
            int hl = idx >> 9, r = (idx >> 2) & 127, c = idx & 3;
            const __nv_bfloat16* src =
                (hl ? Al : Ah) + (size_t)(bm + r) * DH + kk + c * 8;
            cpasync16(sb + (hl * 2560 + r * 20 + c * 4) * 4, src);
        }
        for (int idx = tid; idx < 640; idx += 256) {
            int hl = idx >= 320;
            int j  = idx - hl * 320;
            int r  = j >> 2, c = j & 3;
            const __nv_bfloat16* src =
                (hl ? Bl : Bh) + (size_t)(bn + r) * DH + kk + c * 8;
            cpasync16(sb + (5120 + hl * 1600 + r * 20 + c * 4) * 4, src);
        }
        asm volatile("cp.async.commit_group;");
    };

    const int NT = DH / 32;
    load_tile(0, 0);
    for (int t = 0; t < NT; ++t) {
        int cur = t & 1;
        if (t + 1 < NT) {
            load_tile(cur ^ 1, (t + 1) * 32);
            asm volatile("cp.async.wait_group 1;");
        } else {
            asm volatile("cp.async.wait_group 0;");
        }
        __syncthreads();
        const uint32_t sb = sm0 + cur * GSTAGE * 4;
        uint32_t bh[5][4], bl[5][4];
        #pragma unroll
        for (int nt = 0; nt < 5; ++nt) {
            ldsm4(bh[nt], sb + bOff + nt * 640);
            ldsm4(bl[nt], sb + bOff + nt * 640 + 6400);
        }
        #pragma unroll
        for (int kh = 0; kh < 2; ++kh) {
            const int ks = kh * 8, o = kh * 2;
            uint32_t ah[2][4], al[2][4];
            #pragma unroll
            for (int mt = 0; mt < 2; ++mt) {
                uint32_t a = sb + aOff + (mt * 320 + ks) * 4;
                ldsm4(ah[mt], a);
                ldsm4(al[mt], a + 10240);
            }
            #pragma unroll
            for (int nt = 0; nt < 5; ++nt) {
                #pragma unroll
                for (int mt = 0; mt < 2; ++mt) {
                    mma16816(acc[mt][nt], ah[mt], bh[nt][o], bh[nt][o + 1]);
                    mma16816(acc[mt][nt], ah[mt], bl[nt][o], bl[nt][o + 1]);
                    mma16816(acc[mt][nt], al[mt], bh[nt][o], bh[nt][o + 1]);
                }
            }
        }
        __syncthreads();
    }
    #pragma unroll
    for (int mt = 0; mt < 2; ++mt) {
        #pragma unroll
        for (int nt = 0; nt < 5; ++nt) {
            int r0 = bm + wm * 32 + mt * 16 + g;
            int c0 = bn + wn * 40 + nt * 8 + t4 * 2;
            float b0v = bias[c0], b1v = bias[c0 + 1];
            float x0 = acc[mt][nt][0] + b0v, x1 = acc[mt][nt][1] + b1v;
            float x2 = acc[mt][nt][2] + b0v, x3 = acc[mt][nt][3] + b1v;
            if (act) {
                x0 = 0.5f * x0 * (1.f + erff(x0 * 0.70710678118654752f));
                x1 = 0.5f * x1 * (1.f + erff(x1 * 0.70710678118654752f));
                x2 = 0.5f * x2 * (1.f + erff(x2 * 0.70710678118654752f));
                x3 = 0.5f * x3 * (1.f + erff(x3 * 0.70710678118654752f));
            }
            if (mode == 0) {
                *(float2*)(Cf + (size_t)r0 * DH + c0)       = make_float2(x0, x1);
                *(float2*)(Cf + (size_t)(r0 + 8) * DH + c0) = make_float2(x2, x3);
            } else {
                __nv_bfloat162 h01, h23, l01, l23;
                h01.x = __float2bfloat16(x0); h01.y = __float2bfloat16(x1);
                h23.x = __float2bfloat16(x2); h23.y = __float2bfloat16(x3);
                l01.x = __float2bfloat16(x0 - __bfloat162float(h01.x));
                l01.y = __float2bfloat16(x1 - __bfloat162float(h01.y));
                l23.x = __float2bfloat16(x2 - __bfloat162float(h23.x));
                l23.y = __float2bfloat16(x3 - __bfloat162float(h23.y));
                *(__nv_bfloat162*)(Ch + (size_t)r0 * DH + c0)       = h01;
                *(__nv_bfloat162*)(Ch + (size_t)(r0 + 8) * DH + c0) = h23;
                *(__nv_bfloat162*)(Cl + (size_t)r0 * DH + c0)       = l01;
                *(__nv_bfloat162*)(Cl + (size_t)(r0 + 8) * DH + c0) = l23;
            }
        }
    }
}

// ---- tensor-core attention. smem words: QH 0 QL 1280 | KH 2560 KL 3840
// VH 5120 VL 6400 | QREL 7680 (64x100 f32) | MASS 14080 | RELV 20480 (100x33)
#define ASMEM (23780 * 4)

__global__ __launch_bounds__(128, 2) void attn_mma(
    const __nv_bfloat16* __restrict__ Qh, const __nv_bfloat16* __restrict__ Ql,
    const __nv_bfloat16* __restrict__ Kh, const __nv_bfloat16* __restrict__ Kl,
    const __nv_bfloat16* __restrict__ Vh, const __nv_bfloat16* __restrict__ Vl,
    const float* __restrict__ relk, const float* __restrict__ relv,
    const int* __restrict__ rm,
    __nv_bfloat16* __restrict__ ctxh, __nv_bfloat16* __restrict__ ctxl)
{
    extern __shared__ uint32_t sw[];
    const uint32_t s0 = (uint32_t)__cvta_generic_to_shared(sw);
    float* sf = (float*)sw;
    const int tid = threadIdx.x;
    const int w = tid >> 5, lane = tid & 31;
    const int g = lane >> 2, t4 = lane & 3;
    const int b = blockIdx.x / NHEADS, h = blockIdx.x % NHEADS;
    const int qbase = blockIdx.y * 64;
    const float scale = 0.1767766952966369f;

    // Q tile (64 rows hi/lo), 512 chunks
    #pragma unroll
    for (int it = 0; it < 4; ++it) {
        int idx = tid + it * 128;
        int hl = idx >> 8, r = (idx >> 2) & 63, c = idx & 3;
        cpasync16(s0 + (hl * 1280 + r * 20 + c * 4) * 4,
                  (hl ? Ql : Qh) + (size_t)(b * SEQ + qbase + r) * DH + h * PH + c * 8);
    }
    asm volatile("cp.async.commit_group;");
    for (int i = tid; i < 3200; i += 128)
        sf[20480 + (i >> 5) * 33 + (i & 31)] = relv[i];
    for (int i = tid; i < 6400; i += 128) sf[14080 + i] = 0.f;
    asm volatile("cp.async.wait_group 0;");
    __syncthreads();

    // qrel[q][r] (unscaled)
    {
        int q = tid >> 1, rh = (tid & 1) * 50;
        const __nv_bfloat16* sb = (const __nv_bfloat16*)sw;
        float qv[32];
        #pragma unroll
        for (int d = 0; d < 32; ++d)
            qv[d] = __bfloat162float(sb[q * 40 + d]) +
                    __bfloat162float(sb[2560 + q * 40 + d]);
        for (int r = rh; r < rh + 50; ++r) {
            float a = 0.f;
            #pragma unroll
            for (int d = 0; d < 32; ++d) a = fmaf(qv[d], relk[r * 32 + d], a);
            sf[7680 + q * 100 + r] = a;
        }
    }

    const uint32_t aBase = s0 + ((16 * w + (lane & 7) + 8 * ((lane >> 3) & 1)) * 20
                                + 4 * (lane >> 4)) * 4;
    const uint32_t kBase = s0 + (2560 + (lane & 7) * 20 + 4 * (lane >> 3)) * 4;
    const int vRow = lane & 15;

    float oacc[4][4];
    #pragma unroll
    for (int nd = 0; nd < 4; ++nd)
        #pragma unroll
        for (int i = 0; i < 4; ++i) oacc[nd][i] = 0.f;
    float lg = 0.f, lg8 = 0.f;
    const int rowg = qbase + 16 * w + g;
    const int* rmg  = rm + ((size_t)(b * SEQ + rowg)) * SEQ;
    const int* rmg8 = rmg + 8 * SEQ;
    const float* qrl_g  = sf + 7680 + (16 * w + g) * 100;
    const float* qrl_g8 = qrl_g + 800;
    float* msg  = sf + 14080 + (16 * w + g) * 100;
    float* msg8 = msg + 800;

    for (int ti = 0; ti < 8; ++ti) {
        __syncthreads();
        #pragma unroll
        for (int it = 0; it < 8; ++it) {
            int idx = tid + it * 128;
            int arr = idx >> 8, r = (idx >> 2) & 63, c = idx & 3;
            const __nv_bfloat16* base = arr == 0 ? Kh : arr == 1 ? Kl :
                                        arr == 2 ? Vh : Vl;
            cpasync16(s0 + (2560 + arr * 1280 + r * 20 + c * 4) * 4,
                      base + (size_t)(b * SEQ + ti * 64 + r) * DH + h * PH + c * 8);
        }
        asm volatile("cp.async.commit_group;");
        asm volatile("cp.async.wait_group 0;");
        __syncthreads();

        // S = Q K^T
        float sacc[8][4];
        #pragma unroll
        for (int n = 0; n < 8; ++n)
            #pragma unroll
            for (int i = 0; i < 4; ++i) sacc[n][i] = 0.f;
        uint32_t qf[2][4], qfl[2][4];
        #pragma unroll
        for (int kh = 0; kh < 2; ++kh) {
            ldsm4(qf[kh],  aBase + kh * 32);
            ldsm4(qfl[kh], aBase + kh * 32 + 5120);
        }
        #pragma unroll
        for (int n = 0; n < 8; ++n) {
            uint32_t kb[4], kl_[4];
            ldsm4(kb,  kBase + n * 640);
            ldsm4(kl_, kBase + n * 640 + 5120);
            #pragma unroll
            for (int kh = 0; kh < 2; ++kh) {
                mma16816(sacc[n], qf[kh],  kb[2*kh],  kb[2*kh+1]);
                mma16816(sacc[n], qf[kh],  kl_[2*kh], kl_[2*kh+1]);
                mma16816(sacc[n], qfl[kh], kb[2*kh],  kb[2*kh+1]);
            }
        }

        // p = exp((s + qrel)*scale), unnormalized; mass += p
        uint32_t ph[8][2], pl[8][2];
        #pragma unroll
        for (int n = 0; n < 8; ++n) {
            int k0 = ti * 64 + n * 8 + 2 * t4;
            int2 r2  = *(const int2*)&rmg[k0];
            int2 r28 = *(const int2*)&rmg8[k0];
            float p0 = __expf((sacc[n][0] + qrl_g[r2.x])   * scale);
            float p1 = __expf((sacc[n][1] + qrl_g[r2.y])   * scale);
            float p2 = __expf((sacc[n][2] + qrl_g8[r28.x]) * scale);
            float p3 = __expf((sacc[n][3] + qrl_g8[r28.y]) * scale);
            lg += p0 + p1; lg8 += p2 + p3;
            atomicAdd(&msg[r2.x],   p0);
            atomicAdd(&msg[r2.y],   p1);
            atomicAdd(&msg8[r28.x], p2);
            atomicAdd(&msg8[r28.y], p3);
            __nv_bfloat16 h0 = __float2bfloat16(p0), h1 = __float2bfloat16(p1);
            __nv_bfloat16 h2 = __float2bfloat16(p2), h3 = __float2bfloat16(p3);
            ph[n][0] = packbf(h0, h1); ph[n][1] = packbf(h2, h3);
            pl[n][0] = packbf(__float2bfloat16(p0 - __bfloat162float(h0)),
                              __float2bfloat16(p1 - __bfloat162float(h1)));
            pl[n][1] = packbf(__float2bfloat16(p2 - __bfloat162float(h2)),
                              __float2bfloat16(p3 - __bfloat162float(h3)));
        }

        // O += P V  (V^T via ldmatrix.trans)
        #pragma unroll
        for (int kc = 0; kc < 4; ++kc) {
            uint32_t pa[4]  = { ph[2*kc][0], ph[2*kc][1], ph[2*kc+1][0], ph[2*kc+1][1] };
            uint32_t pal[4] = { pl[2*kc][0], pl[2*kc][1], pl[2*kc+1][0], pl[2*kc+1][1] };
            #pragma unroll
            for (int nd = 0; nd < 4; ++nd) {
                uint32_t vb[2], vl2[2];
                uint32_t va = s0 + (5120 + (16 * kc + vRow) * 20 + nd * 4) * 4;
                ldsm2t(vb,  va);
                ldsm2t(vl2, va + 5120);
                mma16816(oacc[nd], pa,  vb[0],  vb[1]);
                mma16816(oacc[nd], pa,  vl2[0], vl2[1]);
                mma16816(oacc[nd], pal, vb[0],  vb[1]);
            }
        }
    }

    lg  += __shfl_xor_sync(0xffffffffu, lg, 1);
    lg  += __shfl_xor_sync(0xffffffffu, lg, 2);
    lg8 += __shfl_xor_sync(0xffffffffu, lg8, 1);
    lg8 += __shfl_xor_sync(0xffffffffu, lg8, 2);
    __syncthreads();   // all mass adds done

    // rel_v term + normalize + store
    float ag[8], ag8[8];
    #pragma unroll
    for (int i = 0; i < 8; ++i) { ag[i] = 0.f; ag8[i] = 0.f; }
    for (int r = 0; r < NREL; ++r) {
        float mg = msg[r], mg8 = msg8[r];
        const float* rv = sf + 20480 + r * 33;
        #pragma unroll
        for (int nd = 0; nd < 4; ++nd) {
            #pragma unroll
            for (int e = 0; e < 2; ++e) {
                float rvv = rv[nd * 8 + 2 * t4 + e];
                ag[nd * 2 + e]  = fmaf(mg,  rvv, ag[nd * 2 + e]);
                ag8[nd * 2 + e] = fmaf(mg8, rvv, ag8[nd * 2 + e]);
            }
        }
    }
    float ig = 1.f / lg, ig8 = 1.f / lg8;
    size_t og  = (size_t)(b * SEQ + rowg) * DH + h * PH;
    size_t og8 = og + 8 * DH;
    #pragma unroll
    for (int nd = 0; nd < 4; ++nd) {
        int d0 = nd * 8 + 2 * t4;
        float v0 = (oacc[nd][0] + ag[nd*2])    * ig;
        float v1 = (oacc[nd][1] + ag[nd*2+1])  * ig;
        float v2 = (oacc[nd][2] + ag8[nd*2])   * ig8;
        float v3 = (oacc[nd][3] + ag8[nd*2+1]) * ig8;
        __nv_bfloat162 hA, hB, lA, lB;
        hA.x = __float2bfloat16(v0); hA.y = __float2bfloat16(v1);
        hB.x = __float2bfloat16(v2); hB.y = __float2bfloat16(v3);
        lA.x = __float2bfloat16(v0 - __bfloat162float(hA.x));
        lA.y = __float2bfloat16(v1 - __bfloat162float(hA.y));
        lB.x = __float2bfloat16(v2 - __bfloat162float(hB.x));
        lB.y = __float2bfloat16(v3 - __bfloat162float(hB.y));
        *(__nv_bfloat162*)(ctxh + og  + d0) = hA;
        *(__nv_bfloat162*)(ctxh + og8 + d0) = hB;
        *(__nv_bfloat162*)(ctxl + og  + d0) = lA;
        *(__nv_bfloat162*)(ctxl + og8 + d0) = lB;
    }
}

extern "C" void kernel_launch(void* const* d_in, const int* in_sizes, int n_in,
                              void* d_out, int out_size)
{
    const float* hidden = (const float*)d_in[0];
    const float* Wq = (const float*)d_in[1];
    const float* bq = (const float*)d_in[2];
    const float* Wk = (const float*)d_in[3];
    const float* bk = (const float*)d_in[4];
    const float* Wv = (const float*)d_in[5];
    const float* bv = (const float*)d_in[6];
    const float* Wo = (const float*)d_in[7];
    const float* bo = (const float*)d_in[8];
    const float* rke = (const float*)d_in[9];
    const float* rve = (const float*)d_in[10];
    const float* W1 = (const float*)d_in[11];
    const float* b1 = (const float*)d_in[12];
    const float* W2 = (const float*)d_in[13];
    const float* b2 = (const float*)d_in[14];
    const int*   rm = (const int*)d_in[15];
    float* out = (float*)d_out;

    __nv_bfloat16 *hh, *hl, *qh, *ql, *kh, *kl, *vh, *vl;
    __nv_bfloat16 *ch, *cl, *ah, *al, *h1h, *h1l, *Wh, *Wl;
    cudaGetSymbolAddress((void**)&hh, g_hh);  cudaGetSymbolAddress((void**)&hl, g_hl);
    cudaGetSymbolAddress((void**)&qh, g_qh);  cudaGetSymbolAddress((void**)&ql, g_ql);
    cudaGetSymbolAddress((void**)&kh, g_kh);  cudaGetSymbolAddress((void**)&kl, g_kl);
    cudaGetSymbolAddress((void**)&vh, g_vh);  cudaGetSymbolAddress((void**)&vl, g_vl);
    cudaGetSymbolAddress((void**)&ch, g_ch);  cudaGetSymbolAddress((void**)&cl, g_cl);
    cudaGetSymbolAddress((void**)&ah, g_ah);  cudaGetSymbolAddress((void**)&al, g_al);
    cudaGetSymbolAddress((void**)&h1h, g_1h); cudaGetSymbolAddress((void**)&h1l, g_1l);
    cudaGetSymbolAddress((void**)&Wh, g_Wh);  cudaGetSymbolAddress((void**)&Wl, g_Wl);

    cudaFuncSetAttribute(hgemm_v4,
        cudaFuncAttributeMaxDynamicSharedMemorySize, GSMEM);
    cudaFuncSetAttribute(attn_mma,
        cudaFuncAttributeMaxDynamicSharedMemorySize, ASMEM);

    dim3 cb(32, 8), cg(DH / 32, DH / 32, 6);
    convert_weight6<<<cg, cb>>>(Wq, Wk, Wv, Wo, W1, W2, Wh, Wl);
    split_act<<<(TOKS * DH) / (256 * 4), 256>>>(hidden, hh, hl);

    size_t WW = (size_t)DH * DH;
    dim3 gg(DH / 80, TOKS / 128);

    hgemm_v4<<<gg, 256, GSMEM>>>(hh, hl, Wh + 0 * WW, Wl + 0 * WW, bq,
                                 nullptr, qh, ql, 0, 1);
    hgemm_v4<<<gg, 256, GSMEM>>>(hh, hl, Wh + 1 * WW, Wl + 1 * WW, bk,
                                 nullptr, kh, kl, 0, 1);
    hgemm_v4<<<gg, 256, GSMEM>>>(hh, hl, Wh + 2 * WW, Wl + 2 * WW, bv,
                                 nullptr, vh, vl, 0, 1);

    dim3 ag(BATCH * NHEADS, SEQ / 64);   // (200, 8)
    attn_mma<<<ag, 128, ASMEM>>>(qh, ql, kh, kl, vh, vl, rke, rve, rm, ch, cl);

    hgemm_v4<<<gg, 256, GSMEM>>>(ch, cl, Wh + 3 * WW, Wl + 3 * WW, bo,
                                 nullptr, ah, al, 0, 1);
    hgemm_v4<<<gg, 256, GSMEM>>>(ah, al, Wh + 4 * WW, Wl + 4 * WW, b1,
                                 nullptr, h1h, h1l, 1, 1);
    hgemm_v4<<<gg, 256, GSMEM>>>(h1h, h1l, Wh + 5 * WW, Wl + 5 * WW, b2,
                                 out, nullptr, nullptr, 0, 0);
}